// round 1
// baseline (speedup 1.0000x reference)
#include <cuda_runtime.h>
#include <cstdint>

// ---------------- problem constants ----------------
#define Bo 96
#define To 100
#define Do 1024
#define Bw 96
#define Tw 30
#define Dw 768
#define Du 2048
#define Dk 256
#define Dv 256

// ---------------- scratch (__device__ globals; no allocation) ----------------
__device__ float Ku_g[(size_t)Bo * To * Dk];   // [b*100+o][256]
__device__ float Kw_g[(size_t)Bw * Tw * Dk];   // [w*30+t][256]
__device__ float Vo_g[(size_t)Bo * To * Dv];   // [b*100+o][256]
__device__ float Vw_g[(size_t)Bw * Tw * Dv];   // [w*30+t][256]
__device__ float logits_g[(size_t)Bw * Bo * Tw]; // [w][b][t]
__device__ float terms_g[(size_t)Bw * Tw];

// ---------------- generic fp32 GEMM + bias: C[M,N] = A[M,K] @ W[K,N] + b ----------------
// 64x64 tile, 256 threads, 4x4 per thread, K-step 16. M,N multiples of 64; K multiple of 16.
__global__ __launch_bounds__(256) void gemm_bias_k(
    const float* __restrict__ A, const float* __restrict__ W,
    const float* __restrict__ bias, float* __restrict__ C,
    int M, int N, int K)
{
    __shared__ float As[64][17];   // [m][k] padded
    __shared__ float Bs[16][64];   // [k][n]

    const int tid = threadIdx.x;
    const int tx = tid & 15;        // n-group
    const int ty = tid >> 4;        // m-group
    const int m0 = blockIdx.y * 64;
    const int n0 = blockIdx.x * 64;

    float acc[4][4];
#pragma unroll
    for (int i = 0; i < 4; i++)
#pragma unroll
        for (int j = 0; j < 4; j++) acc[i][j] = 0.f;

    const int lk = tid & 15, lm = tid >> 4;   // A load: 16 k x 16 m per pass
    const int ln = tid & 63, lkk = tid >> 6;  // W load: 64 n x 4 k per pass

    for (int k0 = 0; k0 < K; k0 += 16) {
#pragma unroll
        for (int p = 0; p < 4; p++)
            As[lm + p * 16][lk] = A[(size_t)(m0 + lm + p * 16) * K + (k0 + lk)];
#pragma unroll
        for (int p = 0; p < 4; p++)
            Bs[lkk + p * 4][ln] = W[(size_t)(k0 + lkk + p * 4) * N + (n0 + ln)];
        __syncthreads();

#pragma unroll
        for (int k = 0; k < 16; k++) {
            float a0 = As[ty * 4 + 0][k];
            float a1 = As[ty * 4 + 1][k];
            float a2 = As[ty * 4 + 2][k];
            float a3 = As[ty * 4 + 3][k];
            float4 bv = *(const float4*)&Bs[k][tx * 4];
            acc[0][0] += a0 * bv.x; acc[0][1] += a0 * bv.y; acc[0][2] += a0 * bv.z; acc[0][3] += a0 * bv.w;
            acc[1][0] += a1 * bv.x; acc[1][1] += a1 * bv.y; acc[1][2] += a1 * bv.z; acc[1][3] += a1 * bv.w;
            acc[2][0] += a2 * bv.x; acc[2][1] += a2 * bv.y; acc[2][2] += a2 * bv.z; acc[2][3] += a2 * bv.w;
            acc[3][0] += a3 * bv.x; acc[3][1] += a3 * bv.y; acc[3][2] += a3 * bv.z; acc[3][3] += a3 * bv.w;
        }
        __syncthreads();
    }

    float4 bb = *(const float4*)&bias[n0 + tx * 4];
#pragma unroll
    for (int i = 0; i < 4; i++) {
        int row = m0 + ty * 4 + i;
        float4 v;
        v.x = acc[i][0] + bb.x; v.y = acc[i][1] + bb.y;
        v.z = acc[i][2] + bb.z; v.w = acc[i][3] + bb.w;
        *(float4*)&C[(size_t)row * N + n0 + tx * 4] = v;
    }
}

// ---------------- fused attention: per (w,b) block ----------------
// smem layout (floats): Kw_s[32*256]=8192 | S_s[30*104]=3120 | red[240] | buf[8448]
#define SM_KW   0
#define SM_S    8192
#define SM_RED  (8192 + 3120)
#define SM_BUF  (8192 + 3120 + 240)
#define SM_FLOATS (8192 + 3120 + 240 + 8448)   // 20000 floats = 80000 bytes

__global__ __launch_bounds__(256) void attn_k(float* __restrict__ att_out,
                                              float* __restrict__ avo_out)
{
    extern __shared__ float sm[];
    float* Kw_s = sm + SM_KW;
    float* S_s  = sm + SM_S;
    float* red  = sm + SM_RED;
    float* buf  = sm + SM_BUF;

    const int w = blockIdx.x / Bo;
    const int b = blockIdx.x % Bo;
    const int tid = threadIdx.x;
    const int lane = tid & 31;
    const int wid  = tid >> 5;

    // load Kw[w] (30x256), zero-pad rows 30,31
    for (int i = tid; i < 32 * 256; i += 256)
        Kw_s[i] = (i < Tw * 256) ? Kw_g[(size_t)w * Tw * 256 + i] : 0.f;
    __syncthreads();

    // ---- phase B: S[t][o] = dot(Kw[t], Ku[o]) / 16 ----
    {
        const int tg = tid >> 5;   // 0..7
        const int o  = tid & 31;
        for (int oc = 0; oc < 4; oc++) {
            const int ob = oc * 32;
            // load Ku chunk transposed: buf[k*33 + oo]
            for (int i = tid; i < 32 * 256; i += 256) {
                int k = i & 255, oo = i >> 8;
                float v = (ob + oo < To)
                          ? Ku_g[((size_t)b * To + ob + oo) * 256 + k] : 0.f;
                buf[k * 33 + oo] = v;
            }
            __syncthreads();

            float a0 = 0.f, a1 = 0.f, a2 = 0.f, a3 = 0.f;
#pragma unroll 4
            for (int k = 0; k < 256; k++) {
                float bv = buf[k * 33 + o];
                a0 += Kw_s[(tg +  0) * 256 + k] * bv;
                a1 += Kw_s[(tg +  8) * 256 + k] * bv;
                a2 += Kw_s[(tg + 16) * 256 + k] * bv;
                a3 += Kw_s[(tg + 24) * 256 + k] * bv;  // rows 30,31 are zero
            }
            if (ob + o < To) {
                S_s[(tg +  0) * 104 + ob + o] = a0 * 0.0625f;
                S_s[(tg +  8) * 104 + ob + o] = a1 * 0.0625f;
                S_s[(tg + 16) * 104 + ob + o] = a2 * 0.0625f;
                if (tg < 6) S_s[(tg + 24) * 104 + ob + o] = a3 * 0.0625f;
            }
            __syncthreads();
        }
    }

    // ---- phase C: softmax rows over o (100), write att ----
    for (int t = wid; t < Tw; t += 8) {
        float m = -1e30f;
        for (int o = lane; o < To; o += 32) m = fmaxf(m, S_s[t * 104 + o]);
#pragma unroll
        for (int off = 16; off; off >>= 1) m = fmaxf(m, __shfl_xor_sync(0xffffffffu, m, off));
        float s = 0.f;
        for (int o = lane; o < To; o += 32) s += __expf(S_s[t * 104 + o] - m);
#pragma unroll
        for (int off = 16; off; off >>= 1) s += __shfl_xor_sync(0xffffffffu, s, off);
        float inv = 1.f / s;
        size_t base = ((size_t)(w * Bo + b) * Tw + t) * To;
        for (int o = lane; o < To; o += 32) {
            float p = __expf(S_s[t * 104 + o] - m) * inv;
            S_s[t * 104 + o] = p;
            att_out[base + o] = p;
        }
    }
    __syncthreads();

    // ---- phase D: AV[t][d] = sum_o P[t][o] * Vo[b][o][d]; thread owns d ----
    const int d = tid;
    float acc[Tw];
#pragma unroll
    for (int t = 0; t < Tw; t++) acc[t] = 0.f;

    for (int oc = 0; oc < 4; oc++) {
        const int ob = oc * 25;
        for (int i = tid; i < 25 * 256; i += 256) {
            int dd = i & 255, oo = i >> 8;
            buf[oo * 256 + dd] = Vo_g[((size_t)b * To + ob + oo) * 256 + dd];
        }
        __syncthreads();
#pragma unroll 1
        for (int o = 0; o < 25; o++) {
            float v = buf[o * 256 + d];
#pragma unroll
            for (int t = 0; t < Tw; t++)
                acc[t] += S_s[t * 104 + ob + o] * v;
        }
        __syncthreads();
    }

    // ---- phase E: write att_V_o; logits[w][b][t] = dot_d(AV[t], Vw[w][t]) ----
    {
        size_t avo_base = (size_t)(w * Bo + b) * Tw * 256;
        size_t vw_base  = (size_t)w * Tw * 256;
#pragma unroll 1
        for (int t = 0; t < Tw; t++) {
            avo_out[avo_base + (size_t)t * 256 + d] = acc[t];
            float part = acc[t] * Vw_g[vw_base + (size_t)t * 256 + d];
#pragma unroll
            for (int off = 16; off; off >>= 1) part += __shfl_xor_sync(0xffffffffu, part, off);
            if (lane == 0) red[t * 8 + wid] = part;
        }
        __syncthreads();
        if (tid < Tw) {
            float s = 0.f;
#pragma unroll
            for (int j = 0; j < 8; j++) s += red[tid * 8 + j];
            logits_g[((size_t)w * Bo + b) * Tw + tid] = s;
        }
    }
}

// ---------------- loss terms: one warp per (w,t); LSE over b ----------------
__global__ __launch_bounds__(32) void loss_terms_k(const float* __restrict__ mask)
{
    const int idx = blockIdx.x;
    const int w = idx / Tw, t = idx % Tw;
    const int lane = threadIdx.x;

    float m = -1e30f;
    for (int b = lane; b < Bo; b += 32)
        m = fmaxf(m, logits_g[((size_t)w * Bo + b) * Tw + t]);
#pragma unroll
    for (int off = 16; off; off >>= 1) m = fmaxf(m, __shfl_xor_sync(0xffffffffu, m, off));

    float s = 0.f;
    for (int b = lane; b < Bo; b += 32)
        s += __expf(logits_g[((size_t)w * Bo + b) * Tw + t] - m);
#pragma unroll
    for (int off = 16; off; off >>= 1) s += __shfl_xor_sync(0xffffffffu, s, off);
    float lse = m + __logf(s);

    float nm = (lane < Tw) ? (1.f - mask[w * Tw + lane]) : 0.f;
#pragma unroll
    for (int off = 16; off; off >>= 1) nm += __shfl_xor_sync(0xffffffffu, nm, off);

    if (lane == 0) {
        float diag = logits_g[((size_t)w * Bo + w) * Tw + t];
        float term = (1.f - mask[w * Tw + t]) * (diag - lse) / (nm + 1e-6f);
        terms_g[w * Tw + t] = term;
    }
}

__global__ __launch_bounds__(256) void loss_final_k(float* __restrict__ out)
{
    __shared__ float sh[256];
    float s = 0.f;
    for (int i = threadIdx.x; i < Bw * Tw; i += 256) s += terms_g[i];
    sh[threadIdx.x] = s;
    __syncthreads();
#pragma unroll
    for (int off = 128; off; off >>= 1) {
        if (threadIdx.x < off) sh[threadIdx.x] += sh[threadIdx.x + off];
        __syncthreads();
    }
    if (threadIdx.x == 0) out[0] = -sh[0] / (float)Bw;
}

// ---------------- launch ----------------
extern "C" void kernel_launch(void* const* d_in, const int* in_sizes, int n_in,
                              void* d_out, int out_size)
{
    const float* o    = (const float*)d_in[0];
    const float* u    = (const float*)d_in[1];
    const float* w    = (const float*)d_in[2];
    const float* mask = (const float*)d_in[3];
    const float* Wku  = (const float*)d_in[4];
    const float* bku  = (const float*)d_in[5];
    const float* Wkw  = (const float*)d_in[6];
    const float* bkw  = (const float*)d_in[7];
    const float* Wfo  = (const float*)d_in[8];
    const float* bfo  = (const float*)d_in[9];
    const float* Wfw  = (const float*)d_in[10];
    const float* bfw  = (const float*)d_in[11];

    float* out = (float*)d_out;
    float* att_out = out + 1;
    float* avo_out = out + 1 + (size_t)Bw * Bo * Tw * To;

    float *pKu, *pKw, *pVo, *pVw;
    cudaGetSymbolAddress((void**)&pKu, Ku_g);
    cudaGetSymbolAddress((void**)&pKw, Kw_g);
    cudaGetSymbolAddress((void**)&pVo, Vo_g);
    cudaGetSymbolAddress((void**)&pVw, Vw_g);

    // 4 projection GEMMs
    gemm_bias_k<<<dim3(Dk / 64, (Bo * To) / 64), 256>>>(u, Wku, bku, pKu, Bo * To, Dk, Du);
    gemm_bias_k<<<dim3(Dk / 64, (Bw * Tw) / 64), 256>>>(w, Wkw, bkw, pKw, Bw * Tw, Dk, Dw);
    gemm_bias_k<<<dim3(Dv / 64, (Bo * To) / 64), 256>>>(o, Wfo, bfo, pVo, Bo * To, Dv, Do);
    gemm_bias_k<<<dim3(Dv / 64, (Bw * Tw) / 64), 256>>>(w, Wfw, bfw, pVw, Bw * Tw, Dv, Dw);

    // fused attention
    const int smem_bytes = SM_FLOATS * sizeof(float);
    cudaFuncSetAttribute(attn_k, cudaFuncAttributeMaxDynamicSharedMemorySize, smem_bytes);
    attn_k<<<Bw * Bo, 256, smem_bytes>>>(att_out, avo_out);

    // loss
    loss_terms_k<<<Bw * Tw, 32>>>(mask);
    loss_final_k<<<1, 256>>>(out);
}

// round 2
// speedup vs baseline: 1.6932x; 1.6932x over previous
#include <cuda_runtime.h>
#include <cstdint>

// ---------------- problem constants ----------------
#define Bo 96
#define To 100
#define Do 1024
#define Bw 96
#define Tw 30
#define Dw 768
#define Du 2048
#define Dk 256
#define Dv 256

// ---------------- scratch (__device__ globals; no allocation) ----------------
__device__ float Ku_g[(size_t)Bo * To * Dk];     // [b*100+o][256]
__device__ float Kw_g[(size_t)Bw * Tw * Dk];     // [w*30+t][256]
__device__ float Vo_g[(size_t)Bo * To * Dv];     // [b*100+o][256]
__device__ float Vw_g[(size_t)Bw * Tw * Dv];     // [w*30+t][256]
__device__ float S_g[(size_t)Bw * Tw * Bo * To]; // [w*30+t][b*100+o] pre-softmax logits/16
__device__ float logits_g[(size_t)Bw * Bo * Tw]; // [(w*96+b)*30+t]
__device__ float terms_g[(size_t)Bw * Tw];

// =====================================================================
// Unified 128x128x16 fp32 GEMM, 256 threads, 8x8 microtile.
// MODE 0: C[M,N] = A[M,K] @ B[K,N] + bias        (aligned, K%16==0)
// MODE 1: C[M,N] = (A[M,K] @ B[N,K]^T) * 1/16    (S; aligned, K%16==0)
// MODE 2: batched (z=b): A rows scattered in att layout (4B-aligned only,
//         scalar loads), B = Vo + b*100*256, K=100 (guarded),
//         out scattered to avo layout (scalar stores)
// =====================================================================
template<int MODE>
__global__ __launch_bounds__(256) void gemm_k(
    const float* __restrict__ A, const float* __restrict__ Bp,
    const float* __restrict__ bias, float* __restrict__ C,
    const int M, const int N, const int K)
{
    __shared__ float As[16][132];
    __shared__ float Bs[16][132];
    const int tid = threadIdx.x;
    const int tx = tid & 15, ty = tid >> 4;
    const int m0 = blockIdx.y * 128;
    const int n0 = blockIdx.x * 128;

    int bb = 0;
    const float* Bbase = Bp;
    if (MODE == 2) { bb = blockIdx.z; Bbase = Bp + (size_t)bb * 100 * 256; }

    // ---- A loader mapping: two rows per thread, 4 consecutive k (one f4) ----
    const int ac = tid & 3;          // k f4-column within tile
    const int am = tid >> 2;         // row 0..63 (and +64)
    size_t abase[2]; bool avalid[2];
#pragma unroll
    for (int p = 0; p < 2; p++) {
        int m = m0 + am + p * 64;
        avalid[p] = (m < M);
        int mm = avalid[p] ? m : 0;
        if (MODE == 2) {
            int w_ = mm / 30, t_ = mm % 30;
            abase[p] = ((size_t)(w_ * 96 + bb) * 30 + t_) * 100;
        } else {
            abase[p] = (size_t)mm * K;
        }
    }

    // ---- B loader mapping ----
    const int bk  = tid >> 5;        // MODE 0/2: k row 0..7 (and +8)
    const int bnc = tid & 31;        //            n f4-col 0..31
    const int bn  = tid >> 2;        // MODE 1: B row (n) 0..63 (and +64)
    const int bc  = tid & 3;         //            k f4-col

    float acc[8][8];
#pragma unroll
    for (int i = 0; i < 8; i++)
#pragma unroll
        for (int j = 0; j < 8; j++) acc[i][j] = 0.f;

    for (int k0 = 0; k0 < K; k0 += 16) {
        // ---- load A tile -> As[k][m] (transposed) ----
#pragma unroll
        for (int p = 0; p < 2; p++) {
            float4 v = make_float4(0.f, 0.f, 0.f, 0.f);
            bool ok = avalid[p];
            if (MODE == 2) {
                ok = ok && (k0 + ac * 4 < K);
                if (ok) {  // 4B-aligned region: scalar loads
                    const float* pA = A + abase[p] + k0 + ac * 4;
                    v.x = pA[0]; v.y = pA[1]; v.z = pA[2]; v.w = pA[3];
                }
            } else {
                if (ok) v = *(const float4*)(A + abase[p] + k0 + ac * 4);
            }
            As[ac * 4 + 0][am + p * 64] = v.x;
            As[ac * 4 + 1][am + p * 64] = v.y;
            As[ac * 4 + 2][am + p * 64] = v.z;
            As[ac * 4 + 3][am + p * 64] = v.w;
        }
        // ---- load B tile ----
        if (MODE == 1) {
#pragma unroll
            for (int p = 0; p < 2; p++) {
                int n = n0 + bn + p * 64;
                float4 v = make_float4(0.f, 0.f, 0.f, 0.f);
                if (n < N) v = *(const float4*)(Bbase + (size_t)n * K + k0 + bc * 4);
                Bs[bc * 4 + 0][bn + p * 64] = v.x;
                Bs[bc * 4 + 1][bn + p * 64] = v.y;
                Bs[bc * 4 + 2][bn + p * 64] = v.z;
                Bs[bc * 4 + 3][bn + p * 64] = v.w;
            }
        } else {
#pragma unroll
            for (int p = 0; p < 2; p++) {
                int kk = bk + p * 8;
                float4 v = make_float4(0.f, 0.f, 0.f, 0.f);
                bool ok = (MODE != 2) || (k0 + kk < K);
                if (ok) v = *(const float4*)(Bbase + (size_t)(k0 + kk) * N + n0 + bnc * 4);
                *(float4*)&Bs[kk][bnc * 4] = v;
            }
        }
        __syncthreads();

        // ---- compute ----
#pragma unroll
        for (int k = 0; k < 16; k++) {
            float av[8], bv[8];
            *(float4*)&av[0] = *(const float4*)&As[k][ty * 8];
            *(float4*)&av[4] = *(const float4*)&As[k][ty * 8 + 4];
            *(float4*)&bv[0] = *(const float4*)&Bs[k][tx * 8];
            *(float4*)&bv[4] = *(const float4*)&Bs[k][tx * 8 + 4];
#pragma unroll
            for (int i = 0; i < 8; i++)
#pragma unroll
                for (int j = 0; j < 8; j++)
                    acc[i][j] += av[i] * bv[j];
        }
        __syncthreads();
    }

    // ---- epilogue ----
    if (MODE == 0) {
        float4 b0 = *(const float4*)(bias + n0 + tx * 8);
        float4 b1 = *(const float4*)(bias + n0 + tx * 8 + 4);
#pragma unroll
        for (int i = 0; i < 8; i++) {
            int m = m0 + ty * 8 + i;
            if (m < M) {
                float4 v0, v1;
                v0.x = acc[i][0] + b0.x; v0.y = acc[i][1] + b0.y;
                v0.z = acc[i][2] + b0.z; v0.w = acc[i][3] + b0.w;
                v1.x = acc[i][4] + b1.x; v1.y = acc[i][5] + b1.y;
                v1.z = acc[i][6] + b1.z; v1.w = acc[i][7] + b1.w;
                *(float4*)(C + (size_t)m * N + n0 + tx * 8)     = v0;
                *(float4*)(C + (size_t)m * N + n0 + tx * 8 + 4) = v1;
            }
        }
    } else if (MODE == 1) {
#pragma unroll
        for (int i = 0; i < 8; i++) {
            int m = m0 + ty * 8 + i;
            if (m < M) {
                float4 v0, v1;
                v0.x = acc[i][0] * 0.0625f; v0.y = acc[i][1] * 0.0625f;
                v0.z = acc[i][2] * 0.0625f; v0.w = acc[i][3] * 0.0625f;
                v1.x = acc[i][4] * 0.0625f; v1.y = acc[i][5] * 0.0625f;
                v1.z = acc[i][6] * 0.0625f; v1.w = acc[i][7] * 0.0625f;
                *(float4*)(C + (size_t)m * N + n0 + tx * 8)     = v0;
                *(float4*)(C + (size_t)m * N + n0 + tx * 8 + 4) = v1;
            }
        }
    } else {
#pragma unroll
        for (int i = 0; i < 8; i++) {
            int m = m0 + ty * 8 + i;
            if (m < M) {
                int w_ = m / 30, t_ = m % 30;
                float* pC = C + ((size_t)(w_ * 96 + bb) * 30 + t_) * 256 + n0 + tx * 8;
#pragma unroll
                for (int j = 0; j < 8; j++) pC[j] = acc[i][j];  // 4B-aligned region
            }
        }
    }
}

// ---------------- softmax: one warp per (w,t,b) row of 100 ----------------
__global__ __launch_bounds__(256) void softmax_k(float* __restrict__ att)
{
    const int gw = blockIdx.x * 8 + (threadIdx.x >> 5);
    const int lane = threadIdx.x & 31;
    const int w = gw / (Tw * Bo);
    const int rem = gw - w * (Tw * Bo);
    const int t = rem / Bo;
    const int b = rem - t * Bo;

    const float* src = S_g + (size_t)(w * Tw + t) * (Bo * To) + b * To;
    float4 v = make_float4(-1e30f, -1e30f, -1e30f, -1e30f);
    if (lane < 25) v = *(const float4*)(src + lane * 4);  // S_g is 16B-aligned

    float m = fmaxf(fmaxf(v.x, v.y), fmaxf(v.z, v.w));
#pragma unroll
    for (int off = 16; off; off >>= 1) m = fmaxf(m, __shfl_xor_sync(0xffffffffu, m, off));

    float4 e;
    e.x = __expf(v.x - m); e.y = __expf(v.y - m);
    e.z = __expf(v.z - m); e.w = __expf(v.w - m);
    float s = e.x + e.y + e.z + e.w;
#pragma unroll
    for (int off = 16; off; off >>= 1) s += __shfl_xor_sync(0xffffffffu, s, off);
    const float inv = 1.f / s;

    if (lane < 25) {  // att region is only 4B-aligned: scalar stores
        float* dst = att + ((size_t)(w * 96 + b) * Tw + t) * To + lane * 4;
        dst[0] = e.x * inv; dst[1] = e.y * inv;
        dst[2] = e.z * inv; dst[3] = e.w * inv;
    }
}

// ---------------- logits: one warp per (w,b,t); dot over 256 ----------------
__global__ __launch_bounds__(256) void logits_k(const float* __restrict__ avo)
{
    const int gw = blockIdx.x * 8 + (threadIdx.x >> 5);
    const int lane = threadIdx.x & 31;
    const int w = gw / (Bo * Tw);
    const int rem = gw - w * (Bo * Tw);
    const int t = rem % Tw;

    const float* av = avo + (size_t)gw * 256;          // 4B-aligned: scalar
    const float* vw = Vw_g + ((size_t)w * Tw + t) * 256;
    float s = 0.f;
#pragma unroll
    for (int c = 0; c < 8; c++) {
        int d = lane + c * 32;
        s += av[d] * vw[d];
    }
#pragma unroll
    for (int off = 16; off; off >>= 1) s += __shfl_xor_sync(0xffffffffu, s, off);
    if (lane == 0) logits_g[gw] = s;
}

// ---------------- loss ----------------
__global__ __launch_bounds__(32) void loss_terms_k(const float* __restrict__ mask)
{
    const int idx = blockIdx.x;
    const int w = idx / Tw, t = idx % Tw;
    const int lane = threadIdx.x;

    float m = -1e30f;
    for (int b = lane; b < Bo; b += 32)
        m = fmaxf(m, logits_g[((size_t)w * Bo + b) * Tw + t]);
#pragma unroll
    for (int off = 16; off; off >>= 1) m = fmaxf(m, __shfl_xor_sync(0xffffffffu, m, off));

    float s = 0.f;
    for (int b = lane; b < Bo; b += 32)
        s += __expf(logits_g[((size_t)w * Bo + b) * Tw + t] - m);
#pragma unroll
    for (int off = 16; off; off >>= 1) s += __shfl_xor_sync(0xffffffffu, s, off);
    float lse = m + __logf(s);

    float nm = (lane < Tw) ? (1.f - mask[w * Tw + lane]) : 0.f;
#pragma unroll
    for (int off = 16; off; off >>= 1) nm += __shfl_xor_sync(0xffffffffu, nm, off);

    if (lane == 0) {
        float diag = logits_g[((size_t)w * Bo + w) * Tw + t];
        terms_g[w * Tw + t] = (1.f - mask[w * Tw + t]) * (diag - lse) / (nm + 1e-6f);
    }
}

__global__ __launch_bounds__(256) void loss_final_k(float* __restrict__ out)
{
    __shared__ float sh[256];
    float s = 0.f;
    for (int i = threadIdx.x; i < Bw * Tw; i += 256) s += terms_g[i];
    sh[threadIdx.x] = s;
    __syncthreads();
#pragma unroll
    for (int off = 128; off; off >>= 1) {
        if (threadIdx.x < off) sh[threadIdx.x] += sh[threadIdx.x + off];
        __syncthreads();
    }
    if (threadIdx.x == 0) out[0] = -sh[0] / (float)Bw;
}

// ---------------- launch ----------------
extern "C" void kernel_launch(void* const* d_in, const int* in_sizes, int n_in,
                              void* d_out, int out_size)
{
    const float* o    = (const float*)d_in[0];
    const float* u    = (const float*)d_in[1];
    const float* w    = (const float*)d_in[2];
    const float* mask = (const float*)d_in[3];
    const float* Wku  = (const float*)d_in[4];
    const float* bku  = (const float*)d_in[5];
    const float* Wkw  = (const float*)d_in[6];
    const float* bkw  = (const float*)d_in[7];
    const float* Wfo  = (const float*)d_in[8];
    const float* bfo  = (const float*)d_in[9];
    const float* Wfw  = (const float*)d_in[10];
    const float* bfw  = (const float*)d_in[11];

    float* out = (float*)d_out;
    float* att_out = out + 1;
    float* avo_out = out + 1 + (size_t)Bw * Bo * Tw * To;

    float *pKu, *pKw, *pVo, *pVw, *pS;
    cudaGetSymbolAddress((void**)&pKu, Ku_g);
    cudaGetSymbolAddress((void**)&pKw, Kw_g);
    cudaGetSymbolAddress((void**)&pVo, Vo_g);
    cudaGetSymbolAddress((void**)&pVw, Vw_g);
    cudaGetSymbolAddress((void**)&pS,  S_g);

    // projections: C = A@W + bias
    gemm_k<0><<<dim3(2, 75), 256>>>(u, Wku, bku, pKu, Bo * To, Dk, Du);
    gemm_k<0><<<dim3(2, 23), 256>>>(w, Wkw, bkw, pKw, Bw * Tw, Dk, Dw);
    gemm_k<0><<<dim3(2, 75), 256>>>(o, Wfo, bfo, pVo, Bo * To, Dv, Do);
    gemm_k<0><<<dim3(2, 23), 256>>>(w, Wfw, bfw, pVw, Bw * Tw, Dv, Dw);

    // S = Kw @ Ku^T / 16   (M=2880, N=9600, K=256)
    gemm_k<1><<<dim3(75, 23), 256>>>(pKw, pKu, nullptr, pS, Bw * Tw, Bo * To, Dk);

    // softmax over o, scatter into att layout
    softmax_k<<<(Bw * Tw * Bo) / 8, 256>>>(att_out);

    // AV: per-b batched (M=2880, N=256, K=100)
    gemm_k<2><<<dim3(2, 23, 96), 256>>>(att_out, pVo, nullptr, avo_out, Bw * Tw, Dv, To);

    // logits + loss
    logits_k<<<(Bw * Bo * Tw) / 8, 256>>>(avo_out);
    loss_terms_k<<<Bw * Tw, 32>>>(mask);
    loss_final_k<<<1, 256>>>(out);
}

// round 3
// speedup vs baseline: 1.8086x; 1.0682x over previous
#include <cuda_runtime.h>
#include <cstdint>

// ---------------- problem constants ----------------
#define Bo 96
#define To 100
#define Do 1024
#define Bw 96
#define Tw 30
#define Dw 768
#define Du 2048
#define Dk 256
#define Dv 256

// ---------------- scratch (__device__ globals; no allocation) ----------------
__device__ __align__(256) float Ku_g[(size_t)Bo * To * Dk];
__device__ __align__(256) float Kw_g[(size_t)Bw * Tw * Dk];
__device__ __align__(256) float Vo_g[(size_t)Bo * To * Dv];
__device__ __align__(256) float Vw_g[(size_t)Bw * Tw * Dv];
__device__ __align__(256) float S_g[(size_t)Bw * Tw * Bo * To];   // [w*30+t][b*100+o]
__device__ __align__(256) float P_g[(size_t)Bw * Bo * Tw * To];   // aligned att copy
__device__ __align__(256) float logits_g[(size_t)Bw * Bo * Tw];
__device__ __align__(256) float terms_g[(size_t)Bw * Tw];

// =====================================================================
// Tiled fp32 GEMM, 256 threads, double-buffered smem, reg-staged prefetch.
// MODE 0: C = A[M,K] @ B[K,N] + bias      (M % BM == 0, K % 16 == 0)
// MODE 1: C = (A[M,K] @ B[N,K]^T) / 16    (N % BN == 0, m guarded)
// MODE 2: batched z=b: A = P_g rows (len K=100, aligned), B = Vo[b],
//         out scattered to avo layout (scalar stores), k guarded
// =====================================================================
template<int BM, int BN, int MODE>
__global__ __launch_bounds__(256) void gemm_k(
    const float* __restrict__ A, const float* __restrict__ Bp,
    const float* __restrict__ bias, float* __restrict__ C,
    const int M, const int N, const int K)
{
    constexpr int TM = BM / 16, TN = BN / 16;
    constexpr int PA = BM / 64;          // A float4 passes
    constexpr int PB = BN / 64;          // B float4 passes
    constexpr int BROW = BN / 4;         // f4 per B row (MODE 0/2)

    __shared__ float As[2][16][BM + 4];
    __shared__ float Bs[2][16][BN + 4];

    const int tid = threadIdx.x;
    const int tx = tid & 15, ty = tid >> 4;
    const int m0 = blockIdx.y * BM;
    const int n0 = blockIdx.x * BN;
    const int bb = (MODE == 2) ? blockIdx.z : 0;
    const float* Bbase = (MODE == 2) ? (Bp + (size_t)bb * 100 * 256) : Bp;

    // ---- A loader: PA rows per thread, one f4 each ----
    const int a_kq = tid & 3;
    const int a_ml = tid >> 2;           // 0..63
    size_t abase[PA];
#pragma unroll
    for (int p = 0; p < PA; p++) {
        int m = m0 + p * 64 + a_ml;
        if (MODE != 0 && m >= M) m = M - 1;
        if (MODE == 2) {
            int w_ = m / 30, t_ = m - w_ * 30;
            abase[p] = ((size_t)(w_ * 96 + bb) * 30 + t_) * 100;
        } else {
            abase[p] = (size_t)m * K;
        }
    }
    // ---- B loader ----
    const int b_kk = tid / BROW;         // MODE 0/2
    const int b_nq = tid % BROW;
    size_t bbase[PB];                    // MODE 1 only
#pragma unroll
    for (int p = 0; p < PB; p++) {
        if (MODE == 1) bbase[p] = (size_t)(n0 + p * 64 + a_ml) * K;
    }

    float4 ra[PA], rb[PB];

    auto ldg = [&](int k0) {
#pragma unroll
        for (int p = 0; p < PA; p++) {
            if (MODE == 2) {
                int ke = k0 + a_kq * 4;
                ra[p] = (ke + 4 <= K) ? *(const float4*)(A + abase[p] + ke)
                                      : make_float4(0.f, 0.f, 0.f, 0.f);
            } else {
                ra[p] = *(const float4*)(A + abase[p] + k0 + a_kq * 4);
            }
        }
#pragma unroll
        for (int p = 0; p < PB; p++) {
            if (MODE == 1) {
                rb[p] = *(const float4*)(Bp + bbase[p] + k0 + a_kq * 4);
            } else {
                int kk = b_kk + p * (256 / BROW);
                rb[p] = (MODE == 2 && k0 + kk >= K)
                        ? make_float4(0.f, 0.f, 0.f, 0.f)
                        : *(const float4*)(Bbase + (size_t)(k0 + kk) * N + n0 + b_nq * 4);
            }
        }
    };
    auto sts = [&](int buf) {
#pragma unroll
        for (int p = 0; p < PA; p++) {
            As[buf][a_kq * 4 + 0][p * 64 + a_ml] = ra[p].x;
            As[buf][a_kq * 4 + 1][p * 64 + a_ml] = ra[p].y;
            As[buf][a_kq * 4 + 2][p * 64 + a_ml] = ra[p].z;
            As[buf][a_kq * 4 + 3][p * 64 + a_ml] = ra[p].w;
        }
#pragma unroll
        for (int p = 0; p < PB; p++) {
            if (MODE == 1) {
                Bs[buf][a_kq * 4 + 0][p * 64 + a_ml] = rb[p].x;
                Bs[buf][a_kq * 4 + 1][p * 64 + a_ml] = rb[p].y;
                Bs[buf][a_kq * 4 + 2][p * 64 + a_ml] = rb[p].z;
                Bs[buf][a_kq * 4 + 3][p * 64 + a_ml] = rb[p].w;
            } else {
                int kk = b_kk + p * (256 / BROW);
                *(float4*)&Bs[buf][kk][b_nq * 4] = rb[p];
            }
        }
    };

    float acc[TM][TN];
#pragma unroll
    for (int i = 0; i < TM; i++)
#pragma unroll
        for (int j = 0; j < TN; j++) acc[i][j] = 0.f;

    auto compute = [&](int buf) {
#pragma unroll
        for (int k = 0; k < 16; k++) {
            float av[TM], bv[TN];
#pragma unroll
            for (int q = 0; q < TM / 4; q++)
                *(float4*)&av[q * 4] = *(const float4*)&As[buf][k][ty * TM + q * 4];
#pragma unroll
            for (int q = 0; q < TN / 4; q++)
                *(float4*)&bv[q * 4] = *(const float4*)&Bs[buf][k][tx * TN + q * 4];
#pragma unroll
            for (int i = 0; i < TM; i++)
#pragma unroll
                for (int j = 0; j < TN; j++)
                    acc[i][j] += av[i] * bv[j];
        }
    };

    // ---- main loop: reg-staged double buffer ----
    ldg(0);
    sts(0);
    __syncthreads();
    int cur = 0;
    for (int k0 = 16; k0 < K + 16; k0 += 16) {
        bool more = (k0 < K);
        if (more) ldg(k0);
        compute(cur);
        if (more) {
            sts(cur ^ 1);
            __syncthreads();
        }
        cur ^= 1;
    }

    // ---- epilogue ----
    if (MODE == 0) {
        float bvals[TN];
#pragma unroll
        for (int q = 0; q < TN / 4; q++)
            *(float4*)&bvals[q * 4] = *(const float4*)(bias + n0 + tx * TN + q * 4);
#pragma unroll
        for (int i = 0; i < TM; i++) {
            int m = m0 + ty * TM + i;
            float* pC = C + (size_t)m * N + n0 + tx * TN;
#pragma unroll
            for (int q = 0; q < TN / 4; q++) {
                float4 v;
                v.x = acc[i][q * 4 + 0] + bvals[q * 4 + 0];
                v.y = acc[i][q * 4 + 1] + bvals[q * 4 + 1];
                v.z = acc[i][q * 4 + 2] + bvals[q * 4 + 2];
                v.w = acc[i][q * 4 + 3] + bvals[q * 4 + 3];
                *(float4*)(pC + q * 4) = v;
            }
        }
    } else if (MODE == 1) {
#pragma unroll
        for (int i = 0; i < TM; i++) {
            int m = m0 + ty * TM + i;
            if (m < M) {
                float* pC = C + (size_t)m * N + n0 + tx * TN;
#pragma unroll
                for (int q = 0; q < TN / 4; q++) {
                    float4 v;
                    v.x = acc[i][q * 4 + 0] * 0.0625f;
                    v.y = acc[i][q * 4 + 1] * 0.0625f;
                    v.z = acc[i][q * 4 + 2] * 0.0625f;
                    v.w = acc[i][q * 4 + 3] * 0.0625f;
                    *(float4*)(pC + q * 4) = v;
                }
            }
        }
    } else {
#pragma unroll
        for (int i = 0; i < TM; i++) {
            int m = m0 + ty * TM + i;
            if (m < M) {
                int w_ = m / 30, t_ = m - w_ * 30;
                float* pC = C + ((size_t)(w_ * 96 + bb) * 30 + t_) * 256 + n0 + tx * TN;
#pragma unroll
                for (int j = 0; j < TN; j++) pC[j] = acc[i][j];  // 4B-aligned region
            }
        }
    }
}

// ---------------- softmax: one warp per (w,t,b) row of 100 ----------------
__global__ __launch_bounds__(256) void softmax_k(float* __restrict__ att,
                                                 float* __restrict__ P)
{
    const int gw = blockIdx.x * 8 + (threadIdx.x >> 5);
    const int lane = threadIdx.x & 31;
    const int w = gw / (Tw * Bo);
    const int rem = gw - w * (Tw * Bo);
    const int t = rem / Bo;
    const int b = rem - t * Bo;

    const float* src = S_g + (size_t)(w * Tw + t) * (Bo * To) + b * To;
    float4 v = make_float4(-1e30f, -1e30f, -1e30f, -1e30f);
    if (lane < 25) v = *(const float4*)(src + lane * 4);

    float m = fmaxf(fmaxf(v.x, v.y), fmaxf(v.z, v.w));
#pragma unroll
    for (int off = 16; off; off >>= 1) m = fmaxf(m, __shfl_xor_sync(0xffffffffu, m, off));

    float4 e;
    e.x = __expf(v.x - m); e.y = __expf(v.y - m);
    e.z = __expf(v.z - m); e.w = __expf(v.w - m);
    float s = e.x + e.y + e.z + e.w;
#pragma unroll
    for (int off = 16; off; off >>= 1) s += __shfl_xor_sync(0xffffffffu, s, off);
    const float inv = 1.f / s;

    if (lane < 25) {
        size_t rbase = ((size_t)(w * 96 + b) * Tw + t) * To + lane * 4;
        float4 r;
        r.x = e.x * inv; r.y = e.y * inv; r.z = e.z * inv; r.w = e.w * inv;
        *(float4*)(P + rbase) = r;          // aligned scratch for AV GEMM
        float* dst = att + rbase;           // 4B-aligned output: scalar
        dst[0] = r.x; dst[1] = r.y; dst[2] = r.z; dst[3] = r.w;
    }
}

// ---------------- logits: one warp per (w,b,t); dot over 256 ----------------
__global__ __launch_bounds__(256) void logits_k(const float* __restrict__ avo)
{
    const int gw = blockIdx.x * 8 + (threadIdx.x >> 5);
    const int lane = threadIdx.x & 31;
    const int w = gw / (Bo * Tw);
    const int rem = gw - w * (Bo * Tw);
    const int t = rem % Tw;

    const float* av = avo + (size_t)gw * 256;
    const float* vw = Vw_g + ((size_t)w * Tw + t) * 256;
    float s = 0.f;
#pragma unroll
    for (int c = 0; c < 8; c++) {
        int d = lane + c * 32;
        s += av[d] * vw[d];
    }
#pragma unroll
    for (int off = 16; off; off >>= 1) s += __shfl_xor_sync(0xffffffffu, s, off);
    if (lane == 0) logits_g[gw] = s;
}

// ---------------- loss ----------------
__global__ __launch_bounds__(32) void loss_terms_k(const float* __restrict__ mask)
{
    const int idx = blockIdx.x;
    const int w = idx / Tw, t = idx % Tw;
    const int lane = threadIdx.x;

    float m = -1e30f;
    for (int b = lane; b < Bo; b += 32)
        m = fmaxf(m, logits_g[((size_t)w * Bo + b) * Tw + t]);
#pragma unroll
    for (int off = 16; off; off >>= 1) m = fmaxf(m, __shfl_xor_sync(0xffffffffu, m, off));

    float s = 0.f;
    for (int b = lane; b < Bo; b += 32)
        s += __expf(logits_g[((size_t)w * Bo + b) * Tw + t] - m);
#pragma unroll
    for (int off = 16; off; off >>= 1) s += __shfl_xor_sync(0xffffffffu, s, off);
    float lse = m + __logf(s);

    float nm = (lane < Tw) ? (1.f - mask[w * Tw + lane]) : 0.f;
#pragma unroll
    for (int off = 16; off; off >>= 1) nm += __shfl_xor_sync(0xffffffffu, nm, off);

    if (lane == 0) {
        float diag = logits_g[((size_t)w * Bo + w) * Tw + t];
        terms_g[w * Tw + t] = (1.f - mask[w * Tw + t]) * (diag - lse) / (nm + 1e-6f);
    }
}

__global__ __launch_bounds__(256) void loss_final_k(float* __restrict__ out)
{
    __shared__ float sh[256];
    float s = 0.f;
    for (int i = threadIdx.x; i < Bw * Tw; i += 256) s += terms_g[i];
    sh[threadIdx.x] = s;
    __syncthreads();
#pragma unroll
    for (int off = 128; off; off >>= 1) {
        if (threadIdx.x < off) sh[threadIdx.x] += sh[threadIdx.x + off];
        __syncthreads();
    }
    if (threadIdx.x == 0) out[0] = -sh[0] / (float)Bw;
}

// ---------------- launch ----------------
extern "C" void kernel_launch(void* const* d_in, const int* in_sizes, int n_in,
                              void* d_out, int out_size)
{
    const float* o    = (const float*)d_in[0];
    const float* u    = (const float*)d_in[1];
    const float* w    = (const float*)d_in[2];
    const float* mask = (const float*)d_in[3];
    const float* Wku  = (const float*)d_in[4];
    const float* bku  = (const float*)d_in[5];
    const float* Wkw  = (const float*)d_in[6];
    const float* bkw  = (const float*)d_in[7];
    const float* Wfo  = (const float*)d_in[8];
    const float* bfo  = (const float*)d_in[9];
    const float* Wfw  = (const float*)d_in[10];
    const float* bfw  = (const float*)d_in[11];

    float* out = (float*)d_out;
    float* att_out = out + 1;
    float* avo_out = out + 1 + (size_t)Bw * Bo * Tw * To;

    float *pKu, *pKw, *pVo, *pVw, *pS, *pP;
    cudaGetSymbolAddress((void**)&pKu, Ku_g);
    cudaGetSymbolAddress((void**)&pKw, Kw_g);
    cudaGetSymbolAddress((void**)&pVo, Vo_g);
    cudaGetSymbolAddress((void**)&pVw, Vw_g);
    cudaGetSymbolAddress((void**)&pS,  S_g);
    cudaGetSymbolAddress((void**)&pP,  P_g);

    // projections
    gemm_k<128, 64, 0><<<dim3(4, 75), 256>>>(u, Wku, bku, pKu, Bo * To, Dk, Du);
    gemm_k<64,  64, 0><<<dim3(4, 45), 256>>>(w, Wkw, bkw, pKw, Bw * Tw, Dk, Dw);
    gemm_k<128, 64, 0><<<dim3(4, 75), 256>>>(o, Wfo, bfo, pVo, Bo * To, Dv, Do);
    gemm_k<64,  64, 0><<<dim3(4, 45), 256>>>(w, Wfw, bfw, pVw, Bw * Tw, Dv, Dw);

    // S = Kw @ Ku^T / 16   (M=2880, N=9600, K=256)
    gemm_k<128, 128, 1><<<dim3(75, 23), 256>>>(pKw, pKu, nullptr, pS, Bw * Tw, Bo * To, Dk);

    // softmax over o, write att (output) + aligned P_g
    softmax_k<<<(Bw * Tw * Bo) / 8, 256>>>(att_out, pP);

    // AV: per-b batched (M=2880, N=256, K=100), A from aligned P_g
    gemm_k<128, 128, 2><<<dim3(2, 23, 96), 256>>>(pP, pVo, nullptr, avo_out, Bw * Tw, Dv, To);

    // logits + loss
    logits_k<<<(Bw * Bo * Tw) / 8, 256>>>(avo_out);
    loss_terms_k<<<Bw * Tw, 32>>>(mask);
    loss_final_k<<<1, 256>>>(out);
}

// round 4
// speedup vs baseline: 3.1526x; 1.7431x over previous
#include <cuda_runtime.h>
#include <cuda_bf16.h>
#include <cstdint>

#define Bo 96
#define To 100
#define Do 1024
#define Bw 96
#define Tw 30
#define Dw 768
#define Du 2048
#define Dk 256
#define Dv 256

typedef __nv_bfloat16 bf16;

// ---------------- scratch (__device__ globals; zero-init, no allocation) ----------------
__device__ __align__(256) bf16 uhi_g[(size_t)Bo * To * Du], ulo_g[(size_t)Bo * To * Du];
__device__ __align__(256) bf16 ohi_g[(size_t)Bo * To * Do], olo_g[(size_t)Bo * To * Do];
__device__ __align__(256) bf16 whi_g[(size_t)Bw * Tw * Dw], wlo_g[(size_t)Bw * Tw * Dw];
__device__ __align__(256) bf16 Wkuhi_g[Du * Dk], Wkulo_g[Du * Dk];
__device__ __align__(256) bf16 Wkwhi_g[Dw * Dk], Wkwlo_g[Dw * Dk];
__device__ __align__(256) bf16 Wfohi_g[Do * Dv], Wfolo_g[Do * Dv];
__device__ __align__(256) bf16 Wfwhi_g[Dw * Dv], Wfwlo_g[Dw * Dv];
__device__ __align__(256) bf16 Kuhi_g[(size_t)Bo * To * Dk], Kulo_g[(size_t)Bo * To * Dk];
__device__ __align__(256) bf16 Kwhi_g[(size_t)Bw * Tw * Dk], Kwlo_g[(size_t)Bw * Tw * Dk];
__device__ __align__(256) bf16 Vohi_g[(size_t)Bo * 128 * Dv], Volo_g[(size_t)Bo * 128 * Dv]; // o padded to 128
__device__ __align__(256) float Vw_g[(size_t)Bw * Tw * Dv];
__device__ __align__(256) float S_g[(size_t)Bw * Tw * Bo * To];     // [w*30+t][b*100+o]
__device__ __align__(256) bf16 Phi_g[(size_t)Bw * Bo * Tw * 128], Plo_g[(size_t)Bw * Bo * Tw * 128]; // o padded
__device__ __align__(256) float logits_g[(size_t)Bw * Bo * Tw];
__device__ __align__(256) float terms_g[(size_t)Bw * Tw];

// ---------------- fp32 -> bf16 hi/lo split ----------------
__global__ __launch_bounds__(256) void split_k(const float* __restrict__ x,
                                               bf16* __restrict__ hi, bf16* __restrict__ lo, int n4)
{
    int i = blockIdx.x * 256 + threadIdx.x;
    if (i >= n4) return;
    float4 v = ((const float4*)x)[i];
    bf16 h0 = __float2bfloat16(v.x); bf16 l0 = __float2bfloat16(v.x - __bfloat162float(h0));
    bf16 h1 = __float2bfloat16(v.y); bf16 l1 = __float2bfloat16(v.y - __bfloat162float(h1));
    bf16 h2 = __float2bfloat16(v.z); bf16 l2 = __float2bfloat16(v.z - __bfloat162float(h2));
    bf16 h3 = __float2bfloat16(v.w); bf16 l3 = __float2bfloat16(v.w - __bfloat162float(h3));
    __nv_bfloat162 a, b;
    a.x = h0; a.y = h1; b.x = h2; b.y = h3;
    ((__nv_bfloat162*)hi)[i * 2] = a; ((__nv_bfloat162*)hi)[i * 2 + 1] = b;
    a.x = l0; a.y = l1; b.x = l2; b.y = l3;
    ((__nv_bfloat162*)lo)[i * 2] = a; ((__nv_bfloat162*)lo)[i * 2 + 1] = b;
}

// ---------------- mma helpers ----------------
__device__ __forceinline__ void ldsm_x4(uint32_t* r, uint32_t addr) {
    asm volatile("ldmatrix.sync.aligned.m8n8.x4.shared.b16 {%0,%1,%2,%3},[%4];"
                 : "=r"(r[0]), "=r"(r[1]), "=r"(r[2]), "=r"(r[3]) : "r"(addr));
}
__device__ __forceinline__ void ldsm_x4t(uint32_t* r, uint32_t addr) {
    asm volatile("ldmatrix.sync.aligned.m8n8.x4.trans.shared.b16 {%0,%1,%2,%3},[%4];"
                 : "=r"(r[0]), "=r"(r[1]), "=r"(r[2]), "=r"(r[3]) : "r"(addr));
}
__device__ __forceinline__ void mma16816(float* c, const uint32_t* a, uint32_t b0, uint32_t b1) {
    asm volatile("mma.sync.aligned.m16n8k16.row.col.f32.bf16.bf16.f32 "
                 "{%0,%1,%2,%3},{%4,%5,%6,%7},{%8,%9},{%0,%1,%2,%3};"
                 : "+f"(c[0]), "+f"(c[1]), "+f"(c[2]), "+f"(c[3])
                 : "r"(a[0]), "r"(a[1]), "r"(a[2]), "r"(a[3]), "r"(b0), "r"(b1));
}
__device__ __forceinline__ void cp16(uint32_t dst, const void* src) {
    asm volatile("cp.async.cg.shared.global [%0],[%1],16;" :: "r"(dst), "l"(src));
}
#define CP_COMMIT() asm volatile("cp.async.commit_group;")
#define CP_WAIT1()  asm volatile("cp.async.wait_group 1;")
#define CP_WAIT0()  asm volatile("cp.async.wait_group 0;")

#define STAGE_SZ 5120   // bf16 elems per (stage,hi/lo) buffer: max(128*40, 32*136)

// =====================================================================
// bf16-split tensor-core GEMM: C = (Ahi+Alo) @ (Bhi+Blo) [3-term]
// Tile 128x128xBK32, 8 warps (4m x 2n), warp tile 32x64.
// MODE 0: proj, fp32 out + bias, B=[K][N]
// MODE 1: proj, split bf16 hi/lo out + bias, B=[K][N], optional vo row remap
// MODE 2: S: B=[N][K] (Ku rows), fp32 out * 1/16
// MODE 3: AV batched (z=b): A rows gathered from P layout, B=Vo[b] [128][256],
//         fp32 out scattered to avo layout (scalar stores)
// =====================================================================
template<int MODE>
__global__ __launch_bounds__(256) void mma_gemm_k(
    const bf16* __restrict__ Ahi, const bf16* __restrict__ Alo,
    const bf16* __restrict__ Bhi, const bf16* __restrict__ Blo,
    const float* __restrict__ bias,
    float* __restrict__ C, bf16* __restrict__ Chi, bf16* __restrict__ Clo,
    const int M, const int N, const int K, const int remap)
{
    extern __shared__ bf16 dyns[];
    const uint32_t sbase = (uint32_t)__cvta_generic_to_shared(dyns);
    constexpr bool BNK = (MODE == 2);
    constexpr int BSTR = BNK ? 40 : 136;

    const int tid = threadIdx.x, lane = tid & 31, w8 = tid >> 5;
    const int wm = w8 & 3, wn = w8 >> 2;
    const int m0 = blockIdx.y * 128, n0 = blockIdx.x * 128;
    const int bb = (MODE == 3) ? blockIdx.z : 0;
    const bf16* BhiB = (MODE == 3) ? (Bhi + (size_t)bb * 128 * 256) : Bhi;
    const bf16* BloB = (MODE == 3) ? (Blo + (size_t)bb * 128 * 256) : Blo;

    // A loader: rows tid>>2 (+64), chunk akq
    const int akq = tid & 3;
    size_t abase[2];
#pragma unroll
    for (int p = 0; p < 2; p++) {
        int m = m0 + p * 64 + (tid >> 2);
        if (m >= M) m = M - 1;
        if (MODE == 3) {
            int w_ = m / 30, t_ = m - w_ * 30;
            abase[p] = ((size_t)(w_ * 96 + bb) * 30 + t_) * 128;
        } else {
            abase[p] = (size_t)m * K;
        }
    }
    // B loader
    size_t bnbase[2];
    const int bkr = tid >> 4;      // KN: k row 0..15
    const int bnq = tid & 15;      // KN: n chunk
#pragma unroll
    for (int p = 0; p < 2; p++)
        if (BNK) bnbase[p] = (size_t)(n0 + p * 64 + (tid >> 2)) * K;

    auto prefetch = [&](int st, int k0) {
#pragma unroll
        for (int hl = 0; hl < 2; hl++) {
            const bf16* as = hl ? Alo : Ahi;
            uint32_t abuf = sbase + (uint32_t)((st * 2 + hl) * STAGE_SZ) * 2;
#pragma unroll
            for (int p = 0; p < 2; p++)
                cp16(abuf + (uint32_t)(((p * 64) + (tid >> 2)) * 40 + akq * 8) * 2,
                     as + abase[p] + k0 + akq * 8);
            const bf16* bs = hl ? BloB : BhiB;
            uint32_t bbuf = sbase + (uint32_t)((4 + st * 2 + hl) * STAGE_SZ) * 2;
            if (BNK) {
#pragma unroll
                for (int p = 0; p < 2; p++)
                    cp16(bbuf + (uint32_t)(((p * 64) + (tid >> 2)) * 40 + akq * 8) * 2,
                         bs + bnbase[p] + k0 + akq * 8);
            } else {
#pragma unroll
                for (int p = 0; p < 2; p++) {
                    int row = p * 16 + bkr;
                    cp16(bbuf + (uint32_t)(row * 136 + bnq * 8) * 2,
                         bs + (size_t)(k0 + row) * N + n0 + bnq * 8);
                }
            }
        }
    };

    float acc[2][8][4];
#pragma unroll
    for (int i = 0; i < 2; i++)
#pragma unroll
        for (int j = 0; j < 8; j++)
#pragma unroll
            for (int q = 0; q < 4; q++) acc[i][j][q] = 0.f;

    const int nsteps = K / 32;
    prefetch(0, 0); CP_COMMIT();
    prefetch(1, 32); CP_COMMIT();
    CP_WAIT1();
    __syncthreads();

    for (int s = 0; s < nsteps; s++) {
        const int st = s & 1;
#pragma unroll
        for (int kk = 0; kk < 2; kk++) {
            uint32_t a[2][2][4];
            const int ar_ = (lane & 7) + ((lane >> 3) & 1) * 8;
            const int ac_ = kk * 16 + ((lane >> 4) << 3);
#pragma unroll
            for (int hl = 0; hl < 2; hl++)
#pragma unroll
                for (int mi = 0; mi < 2; mi++) {
                    int ar = wm * 32 + mi * 16 + ar_;
                    ldsm_x4(a[hl][mi],
                            sbase + (uint32_t)((st * 2 + hl) * STAGE_SZ + ar * 40 + ac_) * 2);
                }
#pragma unroll
            for (int ng = 0; ng < 4; ng++) {
                uint32_t bh[4], bl[4];
                if (BNK) {
                    int br = wn * 64 + ng * 16 + (lane & 7) + ((lane >> 4) << 3);
                    int bc = kk * 16 + ((lane >> 3) & 1) * 8;
                    ldsm_x4(bh, sbase + (uint32_t)((4 + st * 2 + 0) * STAGE_SZ + br * BSTR + bc) * 2);
                    ldsm_x4(bl, sbase + (uint32_t)((4 + st * 2 + 1) * STAGE_SZ + br * BSTR + bc) * 2);
                } else {
                    int br = kk * 16 + (lane & 7) + ((lane >> 3) & 1) * 8;
                    int bc = wn * 64 + ng * 16 + ((lane >> 4) << 3);
                    ldsm_x4t(bh, sbase + (uint32_t)((4 + st * 2 + 0) * STAGE_SZ + br * BSTR + bc) * 2);
                    ldsm_x4t(bl, sbase + (uint32_t)((4 + st * 2 + 1) * STAGE_SZ + br * BSTR + bc) * 2);
                }
#pragma unroll
                for (int n2 = 0; n2 < 2; n2++) {
                    int ni = ng * 2 + n2;
#pragma unroll
                    for (int mi = 0; mi < 2; mi++) {
                        mma16816(acc[mi][ni], a[0][mi], bh[n2 * 2], bh[n2 * 2 + 1]);
                        mma16816(acc[mi][ni], a[0][mi], bl[n2 * 2], bl[n2 * 2 + 1]);
                        mma16816(acc[mi][ni], a[1][mi], bh[n2 * 2], bh[n2 * 2 + 1]);
                    }
                }
            }
        }
        __syncthreads();
        if (s + 2 < nsteps) {
            prefetch(st, (s + 2) * 32); CP_COMMIT(); CP_WAIT1();
        } else {
            CP_WAIT0();
        }
        __syncthreads();
    }

    // ---- epilogue ----
    const int rbase = m0 + wm * 32 + (lane >> 2);
#pragma unroll
    for (int mi = 0; mi < 2; mi++) {
#pragma unroll
        for (int ni = 0; ni < 8; ni++) {
            const int col = n0 + wn * 64 + ni * 8 + (lane & 3) * 2;
            float bv0 = 0.f, bv1 = 0.f;
            if (MODE == 0 || MODE == 1) { bv0 = bias[col]; bv1 = bias[col + 1]; }
#pragma unroll
            for (int h = 0; h < 2; h++) {
                int r = rbase + mi * 16 + h * 8;
                if (r >= M) continue;
                float v0 = acc[mi][ni][h * 2 + 0] + bv0;
                float v1 = acc[mi][ni][h * 2 + 1] + bv1;
                if (MODE == 0) {
                    float2 t; t.x = v0; t.y = v1;
                    *(float2*)(C + (size_t)r * N + col) = t;
                } else if (MODE == 1) {
                    size_t orow = remap ? (size_t)(r / 100) * 128 + (r % 100) : (size_t)r;
                    bf16 h0 = __float2bfloat16(v0);
                    bf16 h1 = __float2bfloat16(v1);
                    __nv_bfloat162 hv, lv;
                    hv.x = h0; hv.y = h1;
                    lv.x = __float2bfloat16(v0 - __bfloat162float(h0));
                    lv.y = __float2bfloat16(v1 - __bfloat162float(h1));
                    *(__nv_bfloat162*)(Chi + orow * 256 + col) = hv;
                    *(__nv_bfloat162*)(Clo + orow * 256 + col) = lv;
                } else if (MODE == 2) {
                    float2 t; t.x = v0 * 0.0625f; t.y = v1 * 0.0625f;
                    *(float2*)(C + (size_t)r * N + col) = t;
                } else {
                    int w_ = r / 30, t_ = r - w_ * 30;
                    float* pC = C + ((size_t)(w_ * 96 + bb) * 30 + t_) * 256 + col;
                    pC[0] = v0; pC[1] = v1;   // 4B-aligned region
                }
            }
        }
    }
}

// ---------------- softmax: one warp per (w,t,b) row of 100; writes att + split P ----------------
__global__ __launch_bounds__(256) void softmax_k(float* __restrict__ att,
                                                 bf16* __restrict__ Phi, bf16* __restrict__ Plo)
{
    const int gw = blockIdx.x * 8 + (threadIdx.x >> 5);
    const int lane = threadIdx.x & 31;
    const int w = gw / (Tw * Bo);
    const int rem = gw - w * (Tw * Bo);
    const int t = rem / Bo;
    const int b = rem - t * Bo;

    const float* src = S_g + (size_t)(w * Tw + t) * (Bo * To) + b * To;
    float4 v = make_float4(-1e30f, -1e30f, -1e30f, -1e30f);
    if (lane < 25) v = *(const float4*)(src + lane * 4);

    float m = fmaxf(fmaxf(v.x, v.y), fmaxf(v.z, v.w));
#pragma unroll
    for (int off = 16; off; off >>= 1) m = fmaxf(m, __shfl_xor_sync(0xffffffffu, m, off));

    float4 e;
    e.x = __expf(v.x - m); e.y = __expf(v.y - m);
    e.z = __expf(v.z - m); e.w = __expf(v.w - m);
    float s = e.x + e.y + e.z + e.w;
#pragma unroll
    for (int off = 16; off; off >>= 1) s += __shfl_xor_sync(0xffffffffu, s, off);
    const float inv = 1.f / s;

    const size_t prow = ((size_t)(w * 96 + b) * Tw + t) * 128 + lane * 4;
    if (lane < 25) {
        float r0 = e.x * inv, r1 = e.y * inv, r2 = e.z * inv, r3 = e.w * inv;
        float* dst = att + ((size_t)(w * 96 + b) * Tw + t) * To + lane * 4;  // 4B-aligned: scalar
        dst[0] = r0; dst[1] = r1; dst[2] = r2; dst[3] = r3;
        __nv_bfloat162 hv, lv;
        bf16 h0 = __float2bfloat16(r0), h1 = __float2bfloat16(r1);
        hv.x = h0; hv.y = h1;
        lv.x = __float2bfloat16(r0 - __bfloat162float(h0));
        lv.y = __float2bfloat16(r1 - __bfloat162float(h1));
        *(__nv_bfloat162*)(Phi + prow) = hv;
        *(__nv_bfloat162*)(Plo + prow) = lv;
        h0 = __float2bfloat16(r2); h1 = __float2bfloat16(r3);
        hv.x = h0; hv.y = h1;
        lv.x = __float2bfloat16(r2 - __bfloat162float(h0));
        lv.y = __float2bfloat16(r3 - __bfloat162float(h1));
        *(__nv_bfloat162*)(Phi + prow + 2) = hv;
        *(__nv_bfloat162*)(Plo + prow + 2) = lv;
    } else {
        __nv_bfloat162 z; z.x = __float2bfloat16(0.f); z.y = z.x;
        *(__nv_bfloat162*)(Phi + prow) = z; *(__nv_bfloat162*)(Phi + prow + 2) = z;
        *(__nv_bfloat162*)(Plo + prow) = z; *(__nv_bfloat162*)(Plo + prow + 2) = z;
    }
}

// ---------------- logits: one warp per (w,b,t); dot over 256 ----------------
__global__ __launch_bounds__(256) void logits_k(const float* __restrict__ avo)
{
    const int gw = blockIdx.x * 8 + (threadIdx.x >> 5);
    const int lane = threadIdx.x & 31;
    const int w = gw / (Bo * Tw);
    const int rem = gw - w * (Bo * Tw);
    const int t = rem % Tw;

    const float* av = avo + (size_t)gw * 256;
    const float* vw = Vw_g + ((size_t)w * Tw + t) * 256;
    float s = 0.f;
#pragma unroll
    for (int c = 0; c < 8; c++) {
        int d = lane + c * 32;
        s += av[d] * vw[d];
    }
#pragma unroll
    for (int off = 16; off; off >>= 1) s += __shfl_xor_sync(0xffffffffu, s, off);
    if (lane == 0) logits_g[gw] = s;
}

// ---------------- loss ----------------
__global__ __launch_bounds__(32) void loss_terms_k(const float* __restrict__ mask)
{
    const int idx = blockIdx.x;
    const int w = idx / Tw, t = idx % Tw;
    const int lane = threadIdx.x;

    float m = -1e30f;
    for (int b = lane; b < Bo; b += 32)
        m = fmaxf(m, logits_g[((size_t)w * Bo + b) * Tw + t]);
#pragma unroll
    for (int off = 16; off; off >>= 1) m = fmaxf(m, __shfl_xor_sync(0xffffffffu, m, off));

    float s = 0.f;
    for (int b = lane; b < Bo; b += 32)
        s += __expf(logits_g[((size_t)w * Bo + b) * Tw + t] - m);
#pragma unroll
    for (int off = 16; off; off >>= 1) s += __shfl_xor_sync(0xffffffffu, s, off);
    float lse = m + __logf(s);

    float nm = (lane < Tw) ? (1.f - mask[w * Tw + lane]) : 0.f;
#pragma unroll
    for (int off = 16; off; off >>= 1) nm += __shfl_xor_sync(0xffffffffu, nm, off);

    if (lane == 0) {
        float diag = logits_g[((size_t)w * Bo + w) * Tw + t];
        terms_g[w * Tw + t] = (1.f - mask[w * Tw + t]) * (diag - lse) / (nm + 1e-6f);
    }
}

__global__ __launch_bounds__(256) void loss_final_k(float* __restrict__ out)
{
    __shared__ float sh[256];
    float s = 0.f;
    for (int i = threadIdx.x; i < Bw * Tw; i += 256) s += terms_g[i];
    sh[threadIdx.x] = s;
    __syncthreads();
#pragma unroll
    for (int off = 128; off; off >>= 1) {
        if (threadIdx.x < off) sh[threadIdx.x] += sh[threadIdx.x + off];
        __syncthreads();
    }
    if (threadIdx.x == 0) out[0] = -sh[0] / (float)Bw;
}

// ---------------- launch ----------------
static inline void* sym(const void* s) { void* p; cudaGetSymbolAddress(&p, s); return p; }

extern "C" void kernel_launch(void* const* d_in, const int* in_sizes, int n_in,
                              void* d_out, int out_size)
{
    const float* o    = (const float*)d_in[0];
    const float* u    = (const float*)d_in[1];
    const float* w    = (const float*)d_in[2];
    const float* mask = (const float*)d_in[3];
    const float* bku  = (const float*)d_in[5];
    const float* bkw  = (const float*)d_in[7];
    const float* bfo  = (const float*)d_in[9];
    const float* bfw  = (const float*)d_in[11];
    const float* Wku  = (const float*)d_in[4];
    const float* Wkw  = (const float*)d_in[6];
    const float* Wfo  = (const float*)d_in[8];
    const float* Wfw  = (const float*)d_in[10];

    float* out = (float*)d_out;
    float* att_out = out + 1;
    float* avo_out = out + 1 + (size_t)Bw * Bo * Tw * To;

    bf16 *uhi = (bf16*)sym(uhi_g), *ulo = (bf16*)sym(ulo_g);
    bf16 *ohi = (bf16*)sym(ohi_g), *olo = (bf16*)sym(olo_g);
    bf16 *whi = (bf16*)sym(whi_g), *wlo = (bf16*)sym(wlo_g);
    bf16 *Wkuhi = (bf16*)sym(Wkuhi_g), *Wkulo = (bf16*)sym(Wkulo_g);
    bf16 *Wkwhi = (bf16*)sym(Wkwhi_g), *Wkwlo = (bf16*)sym(Wkwlo_g);
    bf16 *Wfohi = (bf16*)sym(Wfohi_g), *Wfolo = (bf16*)sym(Wfolo_g);
    bf16 *Wfwhi = (bf16*)sym(Wfwhi_g), *Wfwlo = (bf16*)sym(Wfwlo_g);
    bf16 *Kuhi = (bf16*)sym(Kuhi_g), *Kulo = (bf16*)sym(Kulo_g);
    bf16 *Kwhi = (bf16*)sym(Kwhi_g), *Kwlo = (bf16*)sym(Kwlo_g);
    bf16 *Vohi = (bf16*)sym(Vohi_g), *Volo = (bf16*)sym(Volo_g);
    bf16 *Phi = (bf16*)sym(Phi_g), *Plo = (bf16*)sym(Plo_g);
    float *pVw = (float*)sym(Vw_g), *pS = (float*)sym(S_g);

    const int SMEM = STAGE_SZ * 8 * 2;  // 81920 B
    cudaFuncSetAttribute(mma_gemm_k<0>, cudaFuncAttributeMaxDynamicSharedMemorySize, SMEM);
    cudaFuncSetAttribute(mma_gemm_k<1>, cudaFuncAttributeMaxDynamicSharedMemorySize, SMEM);
    cudaFuncSetAttribute(mma_gemm_k<2>, cudaFuncAttributeMaxDynamicSharedMemorySize, SMEM);
    cudaFuncSetAttribute(mma_gemm_k<3>, cudaFuncAttributeMaxDynamicSharedMemorySize, SMEM);

    // conversions
    auto grid4 = [](size_t n) { return (unsigned)((n / 4 + 255) / 256); };
    split_k<<<grid4((size_t)Bo * To * Du), 256>>>(u, uhi, ulo, Bo * To * Du / 4);
    split_k<<<grid4((size_t)Bo * To * Do), 256>>>(o, ohi, olo, Bo * To * Do / 4);
    split_k<<<grid4((size_t)Bw * Tw * Dw), 256>>>(w, whi, wlo, Bw * Tw * Dw / 4);
    split_k<<<grid4((size_t)Du * Dk), 256>>>(Wku, Wkuhi, Wkulo, Du * Dk / 4);
    split_k<<<grid4((size_t)Dw * Dk), 256>>>(Wkw, Wkwhi, Wkwlo, Dw * Dk / 4);
    split_k<<<grid4((size_t)Do * Dv), 256>>>(Wfo, Wfohi, Wfolo, Do * Dv / 4);
    split_k<<<grid4((size_t)Dw * Dv), 256>>>(Wfw, Wfwhi, Wfwlo, Dw * Dv / 4);

    // projections (tensor core, split outputs)
    mma_gemm_k<1><<<dim3(2, 75), 256, SMEM>>>(uhi, ulo, Wkuhi, Wkulo, bku,
                                              nullptr, Kuhi, Kulo, Bo * To, Dk, Du, 0);
    mma_gemm_k<1><<<dim3(2, 23), 256, SMEM>>>(whi, wlo, Wkwhi, Wkwlo, bkw,
                                              nullptr, Kwhi, Kwlo, Bw * Tw, Dk, Dw, 0);
    mma_gemm_k<1><<<dim3(2, 75), 256, SMEM>>>(ohi, olo, Wfohi, Wfolo, bfo,
                                              nullptr, Vohi, Volo, Bo * To, Dv, Do, 1);
    mma_gemm_k<0><<<dim3(2, 23), 256, SMEM>>>(whi, wlo, Wfwhi, Wfwlo, bfw,
                                              pVw, nullptr, nullptr, Bw * Tw, Dv, Dw, 0);

    // S = Kw @ Ku^T / 16
    mma_gemm_k<2><<<dim3(75, 23), 256, SMEM>>>(Kwhi, Kwlo, Kuhi, Kulo, nullptr,
                                               pS, nullptr, nullptr, Bw * Tw, Bo * To, Dk, 0);

    // softmax -> att + split P (padded K=128)
    softmax_k<<<(Bw * Tw * Bo) / 8, 256>>>(att_out, Phi, Plo);

    // AV batched
    mma_gemm_k<3><<<dim3(2, 23, 96), 256, SMEM>>>(Phi, Plo, Vohi, Volo, nullptr,
                                                  avo_out, nullptr, nullptr, Bw * Tw, Dv, 128, 0);

    // logits + loss
    logits_k<<<(Bw * Bo * Tw) / 8, 256>>>(avo_out);
    loss_terms_k<<<Bw * Tw, 32>>>(mask);
    loss_final_k<<<1, 256>>>(out);
}

// round 5
// speedup vs baseline: 3.5225x; 1.1173x over previous
#include <cuda_runtime.h>
#include <cuda_bf16.h>
#include <cstdint>

#define Bo 96
#define To 100
#define Do 1024
#define Bw 96
#define Tw 30
#define Dw 768
#define Du 2048
#define Dk 256
#define Dv 256

typedef __nv_bfloat16 bf16;

// ---------------- scratch ----------------
__device__ __align__(256) bf16 Wkuhi_g[Du * Dk], Wkulo_g[Du * Dk];
__device__ __align__(256) bf16 Wkwhi_g[Dw * Dk], Wkwlo_g[Dw * Dk];
__device__ __align__(256) bf16 Wfohi_g[Do * Dv], Wfolo_g[Do * Dv];
__device__ __align__(256) bf16 Wfwhi_g[Dw * Dv], Wfwlo_g[Dw * Dv];
__device__ __align__(256) bf16 Kuhi_g[(size_t)Bo * To * Dk], Kulo_g[(size_t)Bo * To * Dk];
__device__ __align__(256) bf16 Kwhi_g[(size_t)Bw * Tw * Dk], Kwlo_g[(size_t)Bw * Tw * Dk];
__device__ __align__(256) bf16 Vohi_g[(size_t)Bo * 128 * Dv], Volo_g[(size_t)Bo * 128 * Dv]; // o pad 128, pad rows stay 0
__device__ __align__(256) float Vw_g[(size_t)Bw * Tw * Dv];
__device__ __align__(256) float S_g[(size_t)Bw * Tw * Bo * To];     // [w*30+t][b*100+o]
__device__ __align__(256) float logits_g[(size_t)Bw * Bo * Tw];
__device__ __align__(256) float terms_g[(size_t)Bw * Tw];

// ---------------- helpers ----------------
__device__ __forceinline__ void ldsm_x4(uint32_t* r, uint32_t addr) {
    asm volatile("ldmatrix.sync.aligned.m8n8.x4.shared.b16 {%0,%1,%2,%3},[%4];"
                 : "=r"(r[0]), "=r"(r[1]), "=r"(r[2]), "=r"(r[3]) : "r"(addr));
}
__device__ __forceinline__ void ldsm_x4t(uint32_t* r, uint32_t addr) {
    asm volatile("ldmatrix.sync.aligned.m8n8.x4.trans.shared.b16 {%0,%1,%2,%3},[%4];"
                 : "=r"(r[0]), "=r"(r[1]), "=r"(r[2]), "=r"(r[3]) : "r"(addr));
}
__device__ __forceinline__ void mma16816(float* c, const uint32_t* a, uint32_t b0, uint32_t b1) {
    asm volatile("mma.sync.aligned.m16n8k16.row.col.f32.bf16.bf16.f32 "
                 "{%0,%1,%2,%3},{%4,%5,%6,%7},{%8,%9},{%0,%1,%2,%3};"
                 : "+f"(c[0]), "+f"(c[1]), "+f"(c[2]), "+f"(c[3])
                 : "r"(a[0]), "r"(a[1]), "r"(a[2]), "r"(a[3]), "r"(b0), "r"(b1));
}
__device__ __forceinline__ void cp16(uint32_t dst, const void* src) {
    asm volatile("cp.async.cg.shared.global [%0],[%1],16;" :: "r"(dst), "l"(src));
}
#define CP_COMMIT() asm volatile("cp.async.commit_group;")
#define CP_WAIT1()  asm volatile("cp.async.wait_group 1;")
#define CP_WAIT0()  asm volatile("cp.async.wait_group 0;")

__device__ __forceinline__ uint32_t pack2(float a, float b) {
    __nv_bfloat162 v = __floats2bfloat162_rn(a, b);
    return *(uint32_t*)&v;
}
__device__ __forceinline__ void split8(const float* f, uint32_t* hi, uint32_t* lo) {
#pragma unroll
    for (int j = 0; j < 4; j++) {
        bf16 h0 = __float2bfloat16(f[2 * j]);
        bf16 h1 = __float2bfloat16(f[2 * j + 1]);
        __nv_bfloat162 hv; hv.x = h0; hv.y = h1;
        hi[j] = *(uint32_t*)&hv;
        lo[j] = pack2(f[2 * j] - __bfloat162float(h0), f[2 * j + 1] - __bfloat162float(h1));
    }
}

// ---------------- weight split (small) ----------------
__global__ __launch_bounds__(256) void split_k(const float* __restrict__ x,
                                               bf16* __restrict__ hi, bf16* __restrict__ lo, int n4)
{
    int i = blockIdx.x * 256 + threadIdx.x;
    if (i >= n4) return;
    float4 v = ((const float4*)x)[i];
    float f[4] = {v.x, v.y, v.z, v.w};
    uint32_t h[2], l[2];
#pragma unroll
    for (int j = 0; j < 2; j++) {
        bf16 h0 = __float2bfloat16(f[2 * j]), h1 = __float2bfloat16(f[2 * j + 1]);
        __nv_bfloat162 hv; hv.x = h0; hv.y = h1;
        h[j] = *(uint32_t*)&hv;
        l[j] = pack2(f[2 * j] - __bfloat162float(h0), f[2 * j + 1] - __bfloat162float(h1));
    }
    ((uint32_t*)hi)[i * 2] = h[0]; ((uint32_t*)hi)[i * 2 + 1] = h[1];
    ((uint32_t*)lo)[i * 2] = l[0]; ((uint32_t*)lo)[i * 2 + 1] = l[1];
}

__global__ __launch_bounds__(1024) void zero_logits_k() {
    logits_g[blockIdx.x * 1024 + threadIdx.x] = 0.f;
}

// =====================================================================
// Projection GEMM: C[M,256] = A_fp32[M,K] @ (Bhi+Blo)[K,256] + bias
// A converted to bf16 hi/lo in-kernel. Tile 128x128x32, 8 warps.
// OUT 0: fp32 C.  OUT 1: split Chi/Clo (+optional o-row remap to 128 pad).
// =====================================================================
#define PAS 5120   // A stage elems (128*40)
#define PBS 4352   // B stage elems (32*136)
template<int OUT>
__global__ __launch_bounds__(256) void proj_k(
    const float* __restrict__ A, const bf16* __restrict__ Bhi, const bf16* __restrict__ Blo,
    const float* __restrict__ bias,
    float* __restrict__ C, bf16* __restrict__ Chi, bf16* __restrict__ Clo,
    const int M, const int K, const int remap)
{
    extern __shared__ bf16 dyns[];
    const uint32_t sbase = (uint32_t)__cvta_generic_to_shared(dyns);
    const int N = 256;

    const int tid = threadIdx.x, lane = tid & 31, w8 = tid >> 5;
    const int wm = w8 & 3, wn = w8 >> 2;
    const int m0 = blockIdx.y * 128, n0 = blockIdx.x * 128;

    const int akq = tid & 3, aml = tid >> 2;
    size_t abase[2];
#pragma unroll
    for (int p = 0; p < 2; p++) {
        int m = m0 + p * 64 + aml;
        if (m >= M) m = M - 1;
        abase[p] = (size_t)m * K;
    }
    const int bkr = tid >> 4, bnq = tid & 15;

    float rA[2][8];
    auto ldgA = [&](int k0) {
#pragma unroll
        for (int p = 0; p < 2; p++) {
            float4 v0 = *(const float4*)(A + abase[p] + k0 + akq * 8);
            float4 v1 = *(const float4*)(A + abase[p] + k0 + akq * 8 + 4);
            rA[p][0] = v0.x; rA[p][1] = v0.y; rA[p][2] = v0.z; rA[p][3] = v0.w;
            rA[p][4] = v1.x; rA[p][5] = v1.y; rA[p][6] = v1.z; rA[p][7] = v1.w;
        }
    };
    auto stsA = [&](int st) {
#pragma unroll
        for (int p = 0; p < 2; p++) {
            uint32_t hi[4], lo[4];
            split8(rA[p], hi, lo);
            uint32_t off = (uint32_t)((p * 64 + aml) * 40 + akq * 8) * 2;
            *(uint4*)(dyns + (st * 2 + 0) * PAS + ((p * 64 + aml) * 40 + akq * 8)) =
                make_uint4(hi[0], hi[1], hi[2], hi[3]);
            *(uint4*)(dyns + (st * 2 + 1) * PAS + ((p * 64 + aml) * 40 + akq * 8)) =
                make_uint4(lo[0], lo[1], lo[2], lo[3]);
            (void)off;
        }
    };
    auto cpB = [&](int k0, int st) {
#pragma unroll
        for (int hl = 0; hl < 2; hl++) {
            const bf16* bs = hl ? Blo : Bhi;
            uint32_t bbuf = sbase + (uint32_t)(4 * PAS + (st * 2 + hl) * PBS) * 2;
#pragma unroll
            for (int p = 0; p < 2; p++) {
                int row = p * 16 + bkr;
                cp16(bbuf + (uint32_t)(row * 136 + bnq * 8) * 2,
                     bs + (size_t)(k0 + row) * N + n0 + bnq * 8);
            }
        }
    };

    float acc[2][8][4];
#pragma unroll
    for (int i = 0; i < 2; i++)
#pragma unroll
        for (int j = 0; j < 8; j++)
#pragma unroll
            for (int q = 0; q < 4; q++) acc[i][j][q] = 0.f;

    auto compute = [&](int st) {
#pragma unroll
        for (int kk = 0; kk < 2; kk++) {
            uint32_t a[2][2][4];
            const int ar_ = (lane & 7) + ((lane >> 3) & 1) * 8;
            const int ac_ = kk * 16 + ((lane >> 4) << 3);
#pragma unroll
            for (int hl = 0; hl < 2; hl++)
#pragma unroll
                for (int mi = 0; mi < 2; mi++) {
                    int ar = wm * 32 + mi * 16 + ar_;
                    ldsm_x4(a[hl][mi], sbase + (uint32_t)((st * 2 + hl) * PAS + ar * 40 + ac_) * 2);
                }
#pragma unroll
            for (int ng = 0; ng < 4; ng++) {
                uint32_t bh[4], bl[4];
                int br = kk * 16 + (lane & 7) + ((lane >> 3) & 1) * 8;
                int bc = wn * 64 + ng * 16 + ((lane >> 4) << 3);
                ldsm_x4t(bh, sbase + (uint32_t)(4 * PAS + (st * 2 + 0) * PBS + br * 136 + bc) * 2);
                ldsm_x4t(bl, sbase + (uint32_t)(4 * PAS + (st * 2 + 1) * PBS + br * 136 + bc) * 2);
#pragma unroll
                for (int n2 = 0; n2 < 2; n2++) {
                    int ni = ng * 2 + n2;
#pragma unroll
                    for (int mi = 0; mi < 2; mi++) {
                        mma16816(acc[mi][ni], a[0][mi], bh[n2 * 2], bh[n2 * 2 + 1]);
                        mma16816(acc[mi][ni], a[0][mi], bl[n2 * 2], bl[n2 * 2 + 1]);
                        mma16816(acc[mi][ni], a[1][mi], bh[n2 * 2], bh[n2 * 2 + 1]);
                    }
                }
            }
        }
    };

    const int nsteps = K / 32;
    ldgA(0); stsA(0);
    cpB(0, 0); CP_COMMIT();
    ldgA(32);
    cpB(32, 1); CP_COMMIT();
    CP_WAIT1();
    __syncthreads();

    for (int s = 0; s < nsteps; s++) {
        const int st = s & 1;
        compute(st);
        if (s + 1 < nsteps) stsA(st ^ 1);
        __syncthreads();
        if (s + 2 < nsteps) {
            ldgA((s + 2) * 32);
            cpB((s + 2) * 32, st); CP_COMMIT(); CP_WAIT1();
        } else {
            CP_WAIT0();
        }
        __syncthreads();
    }

    // epilogue
    const int rbase = m0 + wm * 32 + (lane >> 2);
#pragma unroll
    for (int mi = 0; mi < 2; mi++)
#pragma unroll
        for (int ni = 0; ni < 8; ni++) {
            const int col = n0 + wn * 64 + ni * 8 + (lane & 3) * 2;
            float bv0 = bias[col], bv1 = bias[col + 1];
#pragma unroll
            for (int h = 0; h < 2; h++) {
                int r = rbase + mi * 16 + h * 8;
                if (r >= M) continue;
                float v0 = acc[mi][ni][h * 2 + 0] + bv0;
                float v1 = acc[mi][ni][h * 2 + 1] + bv1;
                if (OUT == 0) {
                    float2 t; t.x = v0; t.y = v1;
                    *(float2*)(C + (size_t)r * N + col) = t;
                } else {
                    size_t orow = remap ? (size_t)(r / 100) * 128 + (r % 100) : (size_t)r;
                    bf16 h0 = __float2bfloat16(v0), h1 = __float2bfloat16(v1);
                    __nv_bfloat162 hv; hv.x = h0; hv.y = h1;
                    *(uint32_t*)(Chi + orow * 256 + col) = *(uint32_t*)&hv;
                    *(uint32_t*)(Clo + orow * 256 + col) =
                        pack2(v0 - __bfloat162float(h0), v1 - __bfloat162float(h1));
                }
            }
        }
}

// =====================================================================
// S GEMM: S = (Kw)(Ku)^T / 16, both pre-split bf16. A[M,K], B[N,K].
// =====================================================================
#define SST 5120
__global__ __launch_bounds__(256) void s_mma_k(
    const bf16* __restrict__ Ahi, const bf16* __restrict__ Alo,
    const bf16* __restrict__ Bhi, const bf16* __restrict__ Blo,
    float* __restrict__ C, const int M, const int N, const int K)
{
    extern __shared__ bf16 dyns[];
    const uint32_t sbase = (uint32_t)__cvta_generic_to_shared(dyns);

    const int tid = threadIdx.x, lane = tid & 31, w8 = tid >> 5;
    const int wm = w8 & 3, wn = w8 >> 2;
    const int m0 = blockIdx.y * 128, n0 = blockIdx.x * 128;

    const int akq = tid & 3, aml = tid >> 2;
    size_t abase[2], bnbase[2];
#pragma unroll
    for (int p = 0; p < 2; p++) {
        int m = m0 + p * 64 + aml;
        if (m >= M) m = M - 1;
        abase[p] = (size_t)m * K;
        bnbase[p] = (size_t)(n0 + p * 64 + aml) * K;
    }

    auto prefetch = [&](int st, int k0) {
#pragma unroll
        for (int hl = 0; hl < 2; hl++) {
            const bf16* as = hl ? Alo : Ahi;
            uint32_t abuf = sbase + (uint32_t)((st * 2 + hl) * SST) * 2;
#pragma unroll
            for (int p = 0; p < 2; p++)
                cp16(abuf + (uint32_t)((p * 64 + aml) * 40 + akq * 8) * 2,
                     as + abase[p] + k0 + akq * 8);
            const bf16* bs = hl ? Blo : Bhi;
            uint32_t bbuf = sbase + (uint32_t)((4 + st * 2 + hl) * SST) * 2;
#pragma unroll
            for (int p = 0; p < 2; p++)
                cp16(bbuf + (uint32_t)((p * 64 + aml) * 40 + akq * 8) * 2,
                     bs + bnbase[p] + k0 + akq * 8);
        }
    };

    float acc[2][8][4];
#pragma unroll
    for (int i = 0; i < 2; i++)
#pragma unroll
        for (int j = 0; j < 8; j++)
#pragma unroll
            for (int q = 0; q < 4; q++) acc[i][j][q] = 0.f;

    const int nsteps = K / 32;
    prefetch(0, 0); CP_COMMIT();
    prefetch(1, 32); CP_COMMIT();
    CP_WAIT1();
    __syncthreads();

    for (int s = 0; s < nsteps; s++) {
        const int st = s & 1;
#pragma unroll
        for (int kk = 0; kk < 2; kk++) {
            uint32_t a[2][2][4];
            const int ar_ = (lane & 7) + ((lane >> 3) & 1) * 8;
            const int ac_ = kk * 16 + ((lane >> 4) << 3);
#pragma unroll
            for (int hl = 0; hl < 2; hl++)
#pragma unroll
                for (int mi = 0; mi < 2; mi++) {
                    int ar = wm * 32 + mi * 16 + ar_;
                    ldsm_x4(a[hl][mi], sbase + (uint32_t)((st * 2 + hl) * SST + ar * 40 + ac_) * 2);
                }
#pragma unroll
            for (int ng = 0; ng < 4; ng++) {
                uint32_t bh[4], bl[4];
                int br = wn * 64 + ng * 16 + (lane & 7) + ((lane >> 4) << 3);
                int bc = kk * 16 + ((lane >> 3) & 1) * 8;
                ldsm_x4(bh, sbase + (uint32_t)((4 + st * 2 + 0) * SST + br * 40 + bc) * 2);
                ldsm_x4(bl, sbase + (uint32_t)((4 + st * 2 + 1) * SST + br * 40 + bc) * 2);
#pragma unroll
                for (int n2 = 0; n2 < 2; n2++) {
                    int ni = ng * 2 + n2;
#pragma unroll
                    for (int mi = 0; mi < 2; mi++) {
                        mma16816(acc[mi][ni], a[0][mi], bh[n2 * 2], bh[n2 * 2 + 1]);
                        mma16816(acc[mi][ni], a[0][mi], bl[n2 * 2], bl[n2 * 2 + 1]);
                        mma16816(acc[mi][ni], a[1][mi], bh[n2 * 2], bh[n2 * 2 + 1]);
                    }
                }
            }
        }
        __syncthreads();
        if (s + 2 < nsteps) {
            prefetch(st, (s + 2) * 32); CP_COMMIT(); CP_WAIT1();
        } else {
            CP_WAIT0();
        }
        __syncthreads();
    }

    const int rbase = m0 + wm * 32 + (lane >> 2);
#pragma unroll
    for (int mi = 0; mi < 2; mi++)
#pragma unroll
        for (int ni = 0; ni < 8; ni++) {
            const int col = n0 + wn * 64 + ni * 8 + (lane & 3) * 2;
#pragma unroll
            for (int h = 0; h < 2; h++) {
                int r = rbase + mi * 16 + h * 8;
                if (r >= M) continue;
                float2 t;
                t.x = acc[mi][ni][h * 2 + 0] * 0.0625f;
                t.y = acc[mi][ni][h * 2 + 1] * 0.0625f;
                *(float2*)(C + (size_t)r * N + col) = t;
            }
        }
}

// =====================================================================
// Fused softmax + AV + logits. grid (2, 23, 96).
// Reads S_g rows, softmax in-warp, writes att (bx==0), builds resident
// P hi/lo smem tiles, MMA against streamed Vo[b], writes avo, atomics logits.
// smem: Phi[128*136] | Plo[128*136] | B stages 2x2x[32*136]
// =====================================================================
#define AV_PLO (128 * 136)
#define AV_BS  (2 * 128 * 136)
#define AV_BST (32 * 136)
__global__ __launch_bounds__(256) void av_fused_k(
    const float* __restrict__ S, const bf16* __restrict__ Vhi, const bf16* __restrict__ Vlo,
    const float* __restrict__ Vw,
    float* __restrict__ att, float* __restrict__ avo)
{
    extern __shared__ bf16 dyns[];
    const uint32_t sbase = (uint32_t)__cvta_generic_to_shared(dyns);

    const int tid = threadIdx.x, lane = tid & 31, w8 = tid >> 5;
    const int wm = w8 & 3, wn = w8 >> 2;
    const int m0 = blockIdx.y * 128, n0 = blockIdx.x * 128;
    const int bb = blockIdx.z;
    const int M = Bw * Tw;

    const int bkr = tid >> 4, bnq = tid & 15;
    auto cpB = [&](int k0, int st) {
#pragma unroll
        for (int hl = 0; hl < 2; hl++) {
            const bf16* bs = hl ? Vlo : Vhi;
            uint32_t bbuf = sbase + (uint32_t)(AV_BS + (st * 2 + hl) * AV_BST) * 2;
#pragma unroll
            for (int p = 0; p < 2; p++) {
                int row = p * 16 + bkr;
                cp16(bbuf + (uint32_t)(row * 136 + bnq * 8) * 2,
                     bs + ((size_t)bb * 128 + k0 + row) * 256 + n0 + bnq * 8);
            }
        }
    };

    // kick off B loads for steps 0,1 (independent of softmax)
    cpB(0, 0); CP_COMMIT();
    cpB(32, 1); CP_COMMIT();

    // ---- softmax phase: warp per row, 16 rows/warp ----
    for (int i = w8; i < 128; i += 8) {
        int m = m0 + i;
        int mc = m < M ? m : M - 1;
        int w_ = mc / 30, t_ = mc - w_ * 30;
        const float* src = S + (size_t)(w_ * 30 + t_) * (Bo * To) + bb * 100;
        float4 v = make_float4(-1e30f, -1e30f, -1e30f, -1e30f);
        if (lane < 25) v = *(const float4*)(src + lane * 4);

        float mx = fmaxf(fmaxf(v.x, v.y), fmaxf(v.z, v.w));
#pragma unroll
        for (int off = 16; off; off >>= 1) mx = fmaxf(mx, __shfl_xor_sync(0xffffffffu, mx, off));
        float4 e;
        e.x = __expf(v.x - mx); e.y = __expf(v.y - mx);
        e.z = __expf(v.z - mx); e.w = __expf(v.w - mx);
        float sm = e.x + e.y + e.z + e.w;
#pragma unroll
        for (int off = 16; off; off >>= 1) sm += __shfl_xor_sync(0xffffffffu, sm, off);
        const float inv = 1.f / sm;

        const int base = i * 136 + lane * 4;
        if (lane < 25) {
            float r0 = e.x * inv, r1 = e.y * inv, r2 = e.z * inv, r3 = e.w * inv;
            if (n0 == 0 && m < M) {
                float* dst = att + ((size_t)(w_ * 96 + bb) * 30 + t_) * 100 + lane * 4;
                dst[0] = r0; dst[1] = r1; dst[2] = r2; dst[3] = r3;
            }
            bf16 h0 = __float2bfloat16(r0), h1 = __float2bfloat16(r1);
            __nv_bfloat162 hv; hv.x = h0; hv.y = h1;
            *(uint32_t*)(dyns + base) = *(uint32_t*)&hv;
            *(uint32_t*)(dyns + AV_PLO + base) =
                pack2(r0 - __bfloat162float(h0), r1 - __bfloat162float(h1));
            h0 = __float2bfloat16(r2); h1 = __float2bfloat16(r3);
            hv.x = h0; hv.y = h1;
            *(uint32_t*)(dyns + base + 2) = *(uint32_t*)&hv;
            *(uint32_t*)(dyns + AV_PLO + base + 2) =
                pack2(r2 - __bfloat162float(h0), r3 - __bfloat162float(h1));
        } else {
            *(uint32_t*)(dyns + base) = 0u;
            *(uint32_t*)(dyns + base + 2) = 0u;
            *(uint32_t*)(dyns + AV_PLO + base) = 0u;
            *(uint32_t*)(dyns + AV_PLO + base + 2) = 0u;
        }
    }
    CP_WAIT1();
    __syncthreads();

    // ---- MMA phase: 4 k-steps, resident A ----
    float acc[2][8][4];
#pragma unroll
    for (int i = 0; i < 2; i++)
#pragma unroll
        for (int j = 0; j < 8; j++)
#pragma unroll
            for (int q = 0; q < 4; q++) acc[i][j][q] = 0.f;

#pragma unroll
    for (int s = 0; s < 4; s++) {
        const int st = s & 1;
#pragma unroll
        for (int kk = 0; kk < 2; kk++) {
            uint32_t a[2][2][4];
            const int ar_ = (lane & 7) + ((lane >> 3) & 1) * 8;
            const int ac_ = s * 32 + kk * 16 + ((lane >> 4) << 3);
#pragma unroll
            for (int hl = 0; hl < 2; hl++)
#pragma unroll
                for (int mi = 0; mi < 2; mi++) {
                    int ar = wm * 32 + mi * 16 + ar_;
                    ldsm_x4(a[hl][mi], sbase + (uint32_t)(hl * AV_PLO + ar * 136 + ac_) * 2);
                }
#pragma unroll
            for (int ng = 0; ng < 4; ng++) {
                uint32_t bh[4], bl[4];
                int br = kk * 16 + (lane & 7) + ((lane >> 3) & 1) * 8;
                int bc = wn * 64 + ng * 16 + ((lane >> 4) << 3);
                ldsm_x4t(bh, sbase + (uint32_t)(AV_BS + (st * 2 + 0) * AV_BST + br * 136 + bc) * 2);
                ldsm_x4t(bl, sbase + (uint32_t)(AV_BS + (st * 2 + 1) * AV_BST + br * 136 + bc) * 2);
#pragma unroll
                for (int n2 = 0; n2 < 2; n2++) {
                    int ni = ng * 2 + n2;
#pragma unroll
                    for (int mi = 0; mi < 2; mi++) {
                        mma16816(acc[mi][ni], a[0][mi], bh[n2 * 2], bh[n2 * 2 + 1]);
                        mma16816(acc[mi][ni], a[0][mi], bl[n2 * 2], bl[n2 * 2 + 1]);
                        mma16816(acc[mi][ni], a[1][mi], bh[n2 * 2], bh[n2 * 2 + 1]);
                    }
                }
            }
        }
        __syncthreads();
        if (s + 2 < 4) {
            cpB((s + 2) * 32, st); CP_COMMIT(); CP_WAIT1();
        } else {
            CP_WAIT0();
        }
        __syncthreads();
    }

    // ---- epilogue: avo stores + logits atomics ----
    const int rbase = m0 + wm * 32 + (lane >> 2);
#pragma unroll
    for (int mi = 0; mi < 2; mi++)
#pragma unroll
        for (int h = 0; h < 2; h++) {
            int r = rbase + mi * 16 + h * 8;
            bool ok = (r < M);
            int rc = ok ? r : M - 1;
            int w_ = rc / 30, t_ = rc - w_ * 30;
            float* prow = avo + ((size_t)(w_ * 96 + bb) * 30 + t_) * 256;
            const float* vwrow = Vw + (size_t)(w_ * 30 + t_) * 256;
            float s = 0.f;
#pragma unroll
            for (int ni = 0; ni < 8; ni++) {
                const int col = n0 + wn * 64 + ni * 8 + (lane & 3) * 2;
                float v0 = acc[mi][ni][h * 2 + 0];
                float v1 = acc[mi][ni][h * 2 + 1];
                if (ok) { prow[col] = v0; prow[col + 1] = v1; }  // 4B-aligned region
                float2 vw2 = *(const float2*)(vwrow + col);
                s += v0 * vw2.x + v1 * vw2.y;
            }
            s += __shfl_xor_sync(0xffffffffu, s, 1);
            s += __shfl_xor_sync(0xffffffffu, s, 2);
            if (ok && (lane & 3) == 0)
                atomicAdd(&logits_g[(size_t)(w_ * 96 + bb) * 30 + t_], s);
        }
}

// ---------------- loss ----------------
__global__ __launch_bounds__(32) void loss_terms_k(const float* __restrict__ mask)
{
    const int idx = blockIdx.x;
    const int w = idx / Tw, t = idx % Tw;
    const int lane = threadIdx.x;

    float m = -1e30f;
    for (int b = lane; b < Bo; b += 32)
        m = fmaxf(m, logits_g[((size_t)w * Bo + b) * Tw + t]);
#pragma unroll
    for (int off = 16; off; off >>= 1) m = fmaxf(m, __shfl_xor_sync(0xffffffffu, m, off));

    float s = 0.f;
    for (int b = lane; b < Bo; b += 32)
        s += __expf(logits_g[((size_t)w * Bo + b) * Tw + t] - m);
#pragma unroll
    for (int off = 16; off; off >>= 1) s += __shfl_xor_sync(0xffffffffu, s, off);
    float lse = m + __logf(s);

    float nm = (lane < Tw) ? (1.f - mask[w * Tw + lane]) : 0.f;
#pragma unroll
    for (int off = 16; off; off >>= 1) nm += __shfl_xor_sync(0xffffffffu, nm, off);

    if (lane == 0) {
        float diag = logits_g[((size_t)w * Bo + w) * Tw + t];
        terms_g[w * Tw + t] = (1.f - mask[w * Tw + t]) * (diag - lse) / (nm + 1e-6f);
    }
}

__global__ __launch_bounds__(256) void loss_final_k(float* __restrict__ out)
{
    __shared__ float sh[256];
    float s = 0.f;
    for (int i = threadIdx.x; i < Bw * Tw; i += 256) s += terms_g[i];
    sh[threadIdx.x] = s;
    __syncthreads();
#pragma unroll
    for (int off = 128; off; off >>= 1) {
        if (threadIdx.x < off) sh[threadIdx.x] += sh[threadIdx.x + off];
        __syncthreads();
    }
    if (threadIdx.x == 0) out[0] = -sh[0] / (float)Bw;
}

// ---------------- launch ----------------
static inline void* sym(const void* s) { void* p; cudaGetSymbolAddress(&p, s); return p; }

extern "C" void kernel_launch(void* const* d_in, const int* in_sizes, int n_in,
                              void* d_out, int out_size)
{
    const float* o    = (const float*)d_in[0];
    const float* u    = (const float*)d_in[1];
    const float* w    = (const float*)d_in[2];
    const float* mask = (const float*)d_in[3];
    const float* Wku  = (const float*)d_in[4];
    const float* bku  = (const float*)d_in[5];
    const float* Wkw  = (const float*)d_in[6];
    const float* bkw  = (const float*)d_in[7];
    const float* Wfo  = (const float*)d_in[8];
    const float* bfo  = (const float*)d_in[9];
    const float* Wfw  = (const float*)d_in[10];
    const float* bfw  = (const float*)d_in[11];

    float* out = (float*)d_out;
    float* att_out = out + 1;
    float* avo_out = out + 1 + (size_t)Bw * Bo * Tw * To;

    bf16 *Wkuhi = (bf16*)sym(Wkuhi_g), *Wkulo = (bf16*)sym(Wkulo_g);
    bf16 *Wkwhi = (bf16*)sym(Wkwhi_g), *Wkwlo = (bf16*)sym(Wkwlo_g);
    bf16 *Wfohi = (bf16*)sym(Wfohi_g), *Wfolo = (bf16*)sym(Wfolo_g);
    bf16 *Wfwhi = (bf16*)sym(Wfwhi_g), *Wfwlo = (bf16*)sym(Wfwlo_g);
    bf16 *Kuhi = (bf16*)sym(Kuhi_g), *Kulo = (bf16*)sym(Kulo_g);
    bf16 *Kwhi = (bf16*)sym(Kwhi_g), *Kwlo = (bf16*)sym(Kwlo_g);
    bf16 *Vohi = (bf16*)sym(Vohi_g), *Volo = (bf16*)sym(Volo_g);
    float *pVw = (float*)sym(Vw_g), *pS = (float*)sym(S_g);

    const int PROJ_SMEM = (4 * PAS + 4 * PBS) * 2;      // 75776
    const int S_SMEM    = SST * 8 * 2;                  // 81920
    const int AV_SMEM   = (AV_BS + 4 * AV_BST) * 2;     // 104448
    cudaFuncSetAttribute(proj_k<0>, cudaFuncAttributeMaxDynamicSharedMemorySize, PROJ_SMEM);
    cudaFuncSetAttribute(proj_k<1>, cudaFuncAttributeMaxDynamicSharedMemorySize, PROJ_SMEM);
    cudaFuncSetAttribute(s_mma_k,   cudaFuncAttributeMaxDynamicSharedMemorySize, S_SMEM);
    cudaFuncSetAttribute(av_fused_k, cudaFuncAttributeMaxDynamicSharedMemorySize, AV_SMEM);

    // weight splits (small)
    auto grid4 = [](size_t n) { return (unsigned)((n / 4 + 255) / 256); };
    split_k<<<grid4((size_t)Du * Dk), 256>>>(Wku, Wkuhi, Wkulo, Du * Dk / 4);
    split_k<<<grid4((size_t)Dw * Dk), 256>>>(Wkw, Wkwhi, Wkwlo, Dw * Dk / 4);
    split_k<<<grid4((size_t)Do * Dv), 256>>>(Wfo, Wfohi, Wfolo, Do * Dv / 4);
    split_k<<<grid4((size_t)Dw * Dv), 256>>>(Wfw, Wfwhi, Wfwlo, Dw * Dv / 4);
    zero_logits_k<<<(Bw * Bo * Tw) / 1024, 1024>>>();

    // projections (A fp32 in-kernel convert)
    proj_k<1><<<dim3(2, 75), 256, PROJ_SMEM>>>(u, Wkuhi, Wkulo, bku, nullptr, Kuhi, Kulo, Bo * To, Du, 0);
    proj_k<1><<<dim3(2, 23), 256, PROJ_SMEM>>>(w, Wkwhi, Wkwlo, bkw, nullptr, Kwhi, Kwlo, Bw * Tw, Dw, 0);
    proj_k<1><<<dim3(2, 75), 256, PROJ_SMEM>>>(o, Wfohi, Wfolo, bfo, nullptr, Vohi, Volo, Bo * To, Do, 1);
    proj_k<0><<<dim3(2, 23), 256, PROJ_SMEM>>>(w, Wfwhi, Wfwlo, bfw, pVw, nullptr, nullptr, Bw * Tw, Dw, 0);

    // S = Kw @ Ku^T / 16
    s_mma_k<<<dim3(75, 23), 256, S_SMEM>>>(Kwhi, Kwlo, Kuhi, Kulo, pS, Bw * Tw, Bo * To, Dk);

    // fused softmax + AV + logits
    av_fused_k<<<dim3(2, 23, 96), 256, AV_SMEM>>>(pS, Vohi, Volo, pVw, att_out, avo_out);

    // loss
    loss_terms_k<<<Bw * Tw, 32>>>(mask);
    loss_final_k<<<1, 256>>>(out);
}

// round 7
// speedup vs baseline: 3.7046x; 1.0517x over previous
#include <cuda_runtime.h>
#include <cuda_bf16.h>
#include <cstdint>

#define Bo 96
#define To 100
#define Do 1024
#define Bw 96
#define Tw 30
#define Dw 768
#define Du 2048
#define Dk 256
#define Dv 256

typedef __nv_bfloat16 bf16;

// ---------------- scratch ----------------
__device__ __align__(256) bf16 Wkuhi_g[Du * Dk], Wkulo_g[Du * Dk];     // [K][N]
__device__ __align__(256) bf16 Wkwhi_g[Dw * Dk], Wkwlo_g[Dw * Dk];
__device__ __align__(256) bf16 Wfohi_g[Do * Dv], Wfolo_g[Do * Dv];
__device__ __align__(256) bf16 Wfwhi_g[Dw * Dv], Wfwlo_g[Dw * Dv];
__device__ __align__(256) bf16 Kuhi_g[(size_t)Bo * To * Dk], Kulo_g[(size_t)Bo * To * Dk];
__device__ __align__(256) bf16 Kwhi_g[(size_t)Bw * Tw * Dk], Kwlo_g[(size_t)Bw * Tw * Dk];
__device__ __align__(256) bf16 Vohi_g[(size_t)Bo * 128 * Dv], Volo_g[(size_t)Bo * 128 * Dv]; // o pad 128
__device__ __align__(256) float Vw_g[(size_t)Bw * Tw * Dv];
__device__ __align__(256) float S_g[(size_t)Bw * Tw * Bo * To];
__device__ __align__(256) float logits_g[(size_t)Bw * Bo * Tw];
__device__ __align__(256) float terms_g[(size_t)Bw * Tw];

// ---------------- helpers ----------------
__device__ __forceinline__ void ldsm_x4(uint32_t* r, uint32_t addr) {
    asm volatile("ldmatrix.sync.aligned.m8n8.x4.shared.b16 {%0,%1,%2,%3},[%4];"
                 : "=r"(r[0]), "=r"(r[1]), "=r"(r[2]), "=r"(r[3]) : "r"(addr));
}
__device__ __forceinline__ void ldsm_x4t(uint32_t* r, uint32_t addr) {
    asm volatile("ldmatrix.sync.aligned.m8n8.x4.trans.shared.b16 {%0,%1,%2,%3},[%4];"
                 : "=r"(r[0]), "=r"(r[1]), "=r"(r[2]), "=r"(r[3]) : "r"(addr));
}
__device__ __forceinline__ void mma16816(float* c, const uint32_t* a, uint32_t b0, uint32_t b1) {
    asm volatile("mma.sync.aligned.m16n8k16.row.col.f32.bf16.bf16.f32 "
                 "{%0,%1,%2,%3},{%4,%5,%6,%7},{%8,%9},{%0,%1,%2,%3};"
                 : "+f"(c[0]), "+f"(c[1]), "+f"(c[2]), "+f"(c[3])
                 : "r"(a[0]), "r"(a[1]), "r"(a[2]), "r"(a[3]), "r"(b0), "r"(b1));
}
__device__ __forceinline__ void cp16(uint32_t dst, const void* src) {
    asm volatile("cp.async.cg.shared.global [%0],[%1],16;" :: "r"(dst), "l"(src));
}
#define CP_COMMIT() asm volatile("cp.async.commit_group;")
#define CP_WAIT1()  asm volatile("cp.async.wait_group 1;")
#define CP_WAIT0()  asm volatile("cp.async.wait_group 0;")

__device__ __forceinline__ uint32_t pack2(float a, float b) {
    __nv_bfloat162 v = __floats2bfloat162_rn(a, b);
    return *(uint32_t*)&v;
}
__device__ __forceinline__ void split8(const float* f, uint32_t* hi, uint32_t* lo) {
#pragma unroll
    for (int j = 0; j < 4; j++) {
        bf16 h0 = __float2bfloat16(f[2 * j]);
        bf16 h1 = __float2bfloat16(f[2 * j + 1]);
        __nv_bfloat162 hv; hv.x = h0; hv.y = h1;
        hi[j] = *(uint32_t*)&hv;
        lo[j] = pack2(f[2 * j] - __bfloat162float(h0), f[2 * j + 1] - __bfloat162float(h1));
    }
}

// ---------------- weight split ----------------
__global__ __launch_bounds__(256) void split_k(const float* __restrict__ x,
                                               bf16* __restrict__ hi, bf16* __restrict__ lo, int n4)
{
    int i = blockIdx.x * 256 + threadIdx.x;
    if (i >= n4) return;
    float4 v = ((const float4*)x)[i];
    float f[4] = {v.x, v.y, v.z, v.w};
    uint32_t h[2], l[2];
#pragma unroll
    for (int j = 0; j < 2; j++) {
        bf16 h0 = __float2bfloat16(f[2 * j]), h1 = __float2bfloat16(f[2 * j + 1]);
        __nv_bfloat162 hv; hv.x = h0; hv.y = h1;
        h[j] = *(uint32_t*)&hv;
        l[j] = pack2(f[2 * j] - __bfloat162float(h0), f[2 * j + 1] - __bfloat162float(h1));
    }
    ((uint32_t*)hi)[i * 2] = h[0]; ((uint32_t*)hi)[i * 2 + 1] = h[1];
    ((uint32_t*)lo)[i * 2] = l[0]; ((uint32_t*)lo)[i * 2 + 1] = l[1];
}

__global__ __launch_bounds__(1024) void zero_logits_k() {
    logits_g[blockIdx.x * 1024 + threadIdx.x] = 0.f;
}

// =====================================================================
// Projection GEMM: C[M,256] = A_fp32[M,K] @ (Bhi+Blo)[K,256] + bias
// 3-stage ring, one __syncthreads per k32 step. Tile 128x128x32, 8 warps.
// OUT 0: fp32 C.  OUT 1: split Chi/Clo (+optional o-row remap to 128 pad).
// KWVW: second B/bias/output set selected by blockIdx.x>=2 (Kw split | Vw fp32).
// =====================================================================
#define PAS 5120   // A stage elems (128*40) per hi/lo
#define PBS 4352   // B stage elems (32*136) per hi/lo
#define PBBASE (6 * PAS)
#define PROJ_SMEM ((6 * PAS + 6 * PBS) * 2)

struct ProjCore {
    uint32_t sbase;
    bf16* dyns;
    int tid, lane, wm, wn;
    float acc[2][8][4];

    __device__ __forceinline__ void init(bf16* d, uint32_t sb, int t) {
        dyns = d; sbase = sb; tid = t; lane = t & 31;
        int w8 = t >> 5; wm = w8 & 3; wn = w8 >> 2;
#pragma unroll
        for (int i = 0; i < 2; i++)
#pragma unroll
            for (int j = 0; j < 8; j++)
#pragma unroll
                for (int q = 0; q < 4; q++) acc[i][j][q] = 0.f;
    }
    __device__ __forceinline__ void stsA(int st, const float rA[2][8], int aml, int akq) {
#pragma unroll
        for (int p = 0; p < 2; p++) {
            uint32_t hi[4], lo[4];
            split8(rA[p], hi, lo);
            int off = (p * 64 + aml) * 40 + akq * 8;
            *(uint4*)(dyns + (st * 2 + 0) * PAS + off) = make_uint4(hi[0], hi[1], hi[2], hi[3]);
            *(uint4*)(dyns + (st * 2 + 1) * PAS + off) = make_uint4(lo[0], lo[1], lo[2], lo[3]);
        }
    }
    __device__ __forceinline__ void compute(int st) {
#pragma unroll
        for (int kk = 0; kk < 2; kk++) {
            uint32_t a[2][2][4];
            const int ar_ = (lane & 7) + ((lane >> 3) & 1) * 8;
            const int ac_ = kk * 16 + ((lane >> 4) << 3);
#pragma unroll
            for (int hl = 0; hl < 2; hl++)
#pragma unroll
                for (int mi = 0; mi < 2; mi++) {
                    int ar = wm * 32 + mi * 16 + ar_;
                    ldsm_x4(a[hl][mi], sbase + (uint32_t)((st * 2 + hl) * PAS + ar * 40 + ac_) * 2);
                }
#pragma unroll
            for (int ng = 0; ng < 4; ng++) {
                uint32_t bh[4], bl[4];
                int br = kk * 16 + (lane & 7) + ((lane >> 3) & 1) * 8;
                int bc = wn * 64 + ng * 16 + ((lane >> 4) << 3);
                ldsm_x4t(bh, sbase + (uint32_t)(PBBASE + (st * 2 + 0) * PBS + br * 136 + bc) * 2);
                ldsm_x4t(bl, sbase + (uint32_t)(PBBASE + (st * 2 + 1) * PBS + br * 136 + bc) * 2);
#pragma unroll
                for (int n2 = 0; n2 < 2; n2++) {
                    int ni = ng * 2 + n2;
#pragma unroll
                    for (int mi = 0; mi < 2; mi++) {
                        mma16816(acc[mi][ni], a[0][mi], bh[n2 * 2], bh[n2 * 2 + 1]);
                        mma16816(acc[mi][ni], a[0][mi], bl[n2 * 2], bl[n2 * 2 + 1]);
                        mma16816(acc[mi][ni], a[1][mi], bh[n2 * 2], bh[n2 * 2 + 1]);
                    }
                }
            }
        }
    }
};

template<int OUT, bool KWVW>
__global__ __launch_bounds__(256) void proj_k(
    const float* __restrict__ A,
    const bf16* __restrict__ Bhi, const bf16* __restrict__ Blo,
    const bf16* __restrict__ B2hi, const bf16* __restrict__ B2lo,
    const float* __restrict__ bias, const float* __restrict__ bias2,
    float* __restrict__ Cf, bf16* __restrict__ Chi, bf16* __restrict__ Clo,
    const int M, const int K, const int remap)
{
    extern __shared__ bf16 dyns[];
    const uint32_t sbase = (uint32_t)__cvta_generic_to_shared(dyns);
    const int N = 256;
    const int tid = threadIdx.x;
    const bool second = KWVW && (blockIdx.x >= 2);
    const int n0 = (KWVW ? (blockIdx.x & 1) : blockIdx.x) * 128;
    const int m0 = blockIdx.y * 128;
    const bf16* bhi = (KWVW && second) ? B2hi : Bhi;
    const bf16* blo = (KWVW && second) ? B2lo : Blo;
    const float* bs = (KWVW && second) ? bias2 : bias;

    const int akq = tid & 3, aml = tid >> 2;
    size_t abase[2];
#pragma unroll
    for (int p = 0; p < 2; p++) {
        int m = m0 + p * 64 + aml;
        if (m >= M) m = M - 1;
        abase[p] = (size_t)m * K;
    }
    const int bkr = tid >> 4, bnq = tid & 15;

    float rA[2][8];
    auto ldgA = [&](int k0) {
#pragma unroll
        for (int p = 0; p < 2; p++) {
            float4 v0 = *(const float4*)(A + abase[p] + k0 + akq * 8);
            float4 v1 = *(const float4*)(A + abase[p] + k0 + akq * 8 + 4);
            rA[p][0] = v0.x; rA[p][1] = v0.y; rA[p][2] = v0.z; rA[p][3] = v0.w;
            rA[p][4] = v1.x; rA[p][5] = v1.y; rA[p][6] = v1.z; rA[p][7] = v1.w;
        }
    };
    auto cpB = [&](int k0, int st) {
#pragma unroll
        for (int hl = 0; hl < 2; hl++) {
            const bf16* bsrc = hl ? blo : bhi;
            uint32_t bbuf = sbase + (uint32_t)(PBBASE + (st * 2 + hl) * PBS) * 2;
#pragma unroll
            for (int p = 0; p < 2; p++) {
                int row = p * 16 + bkr;
                cp16(bbuf + (uint32_t)(row * 136 + bnq * 8) * 2,
                     bsrc + (size_t)(k0 + row) * N + n0 + bnq * 8);
            }
        }
    };

    ProjCore core;
    core.init(dyns, sbase, tid);

    const int nsteps = K / 32;
    ldgA(0); core.stsA(0, rA, aml, akq);
    cpB(0, 0); CP_COMMIT();
    cpB(32, 1); CP_COMMIT();
    ldgA(32);

    for (int s = 0; s < nsteps; s++) {
        if (s == nsteps - 1) { CP_WAIT0(); } else { CP_WAIT1(); }
        if (s + 1 < nsteps) core.stsA((s + 1) % 3, rA, aml, akq);
        __syncthreads();
        if (s + 2 < nsteps) {
            ldgA((s + 2) * 32);
            cpB((s + 2) * 32, (s + 2) % 3); CP_COMMIT();
        }
        core.compute(s % 3);
    }

    // epilogue
    const bool splitOut = (OUT == 1) && !(KWVW && second);
    const int rbase = m0 + core.wm * 32 + (core.lane >> 2);
#pragma unroll
    for (int mi = 0; mi < 2; mi++)
#pragma unroll
        for (int ni = 0; ni < 8; ni++) {
            const int col = n0 + core.wn * 64 + ni * 8 + (core.lane & 3) * 2;
            float bv0 = bs[col], bv1 = bs[col + 1];
#pragma unroll
            for (int h = 0; h < 2; h++) {
                int r = rbase + mi * 16 + h * 8;
                if (r >= M) continue;
                float v0 = core.acc[mi][ni][h * 2 + 0] + bv0;
                float v1 = core.acc[mi][ni][h * 2 + 1] + bv1;
                if (splitOut) {
                    size_t orow = remap ? (size_t)(r / 100) * 128 + (r % 100) : (size_t)r;
                    bf16 h0 = __float2bfloat16(v0), h1 = __float2bfloat16(v1);
                    __nv_bfloat162 hv; hv.x = h0; hv.y = h1;
                    *(uint32_t*)(Chi + orow * 256 + col) = *(uint32_t*)&hv;
                    *(uint32_t*)(Clo + orow * 256 + col) =
                        pack2(v0 - __bfloat162float(h0), v1 - __bfloat162float(h1));
                } else {
                    float2 t; t.x = v0; t.y = v1;
                    *(float2*)(Cf + (size_t)r * N + col) = t;
                }
            }
        }
}

// =====================================================================
// S GEMM: S = (Kw)(Ku)^T / 16, pre-split bf16, A[M,K], B[N,K].
// 3-stage ring, single sync per step.
// =====================================================================
#define SST 5120
#define SBBASE (6 * SST)
#define S_SMEM (12 * SST * 2)
__global__ __launch_bounds__(256) void s_mma_k(
    const bf16* __restrict__ Ahi, const bf16* __restrict__ Alo,
    const bf16* __restrict__ Bhi, const bf16* __restrict__ Blo,
    float* __restrict__ C, const int M, const int N, const int K)
{
    extern __shared__ bf16 dyns[];
    const uint32_t sbase = (uint32_t)__cvta_generic_to_shared(dyns);

    const int tid = threadIdx.x, lane = tid & 31, w8 = tid >> 5;
    const int wm = w8 & 3, wn = w8 >> 2;
    const int m0 = blockIdx.y * 128, n0 = blockIdx.x * 128;

    const int akq = tid & 3, aml = tid >> 2;
    size_t abase[2], bnbase[2];
#pragma unroll
    for (int p = 0; p < 2; p++) {
        int m = m0 + p * 64 + aml;
        if (m >= M) m = M - 1;
        abase[p] = (size_t)m * K;
        bnbase[p] = (size_t)(n0 + p * 64 + aml) * K;
    }

    auto prefetch = [&](int k0, int st) {
#pragma unroll
        for (int hl = 0; hl < 2; hl++) {
            const bf16* as = hl ? Alo : Ahi;
            uint32_t abuf = sbase + (uint32_t)((st * 2 + hl) * SST) * 2;
#pragma unroll
            for (int p = 0; p < 2; p++)
                cp16(abuf + (uint32_t)((p * 64 + aml) * 40 + akq * 8) * 2,
                     as + abase[p] + k0 + akq * 8);
            const bf16* bsrc = hl ? Blo : Bhi;
            uint32_t bbuf = sbase + (uint32_t)(SBBASE + (st * 2 + hl) * SST) * 2;
#pragma unroll
            for (int p = 0; p < 2; p++)
                cp16(bbuf + (uint32_t)((p * 64 + aml) * 40 + akq * 8) * 2,
                     bsrc + bnbase[p] + k0 + akq * 8);
        }
    };

    float acc[2][8][4];
#pragma unroll
    for (int i = 0; i < 2; i++)
#pragma unroll
        for (int j = 0; j < 8; j++)
#pragma unroll
            for (int q = 0; q < 4; q++) acc[i][j][q] = 0.f;

    const int nsteps = K / 32;
    prefetch(0, 0); CP_COMMIT();
    prefetch(32, 1); CP_COMMIT();

    for (int s = 0; s < nsteps; s++) {
        if (s == nsteps - 1) { CP_WAIT0(); } else { CP_WAIT1(); }
        __syncthreads();
        if (s + 2 < nsteps) { prefetch((s + 2) * 32, (s + 2) % 3); CP_COMMIT(); }
        const int st = s % 3;
#pragma unroll
        for (int kk = 0; kk < 2; kk++) {
            uint32_t a[2][2][4];
            const int ar_ = (lane & 7) + ((lane >> 3) & 1) * 8;
            const int ac_ = kk * 16 + ((lane >> 4) << 3);
#pragma unroll
            for (int hl = 0; hl < 2; hl++)
#pragma unroll
                for (int mi = 0; mi < 2; mi++) {
                    int ar = wm * 32 + mi * 16 + ar_;
                    ldsm_x4(a[hl][mi], sbase + (uint32_t)((st * 2 + hl) * SST + ar * 40 + ac_) * 2);
                }
#pragma unroll
            for (int ng = 0; ng < 4; ng++) {
                uint32_t bh[4], bl[4];
                int br = wn * 64 + ng * 16 + (lane & 7) + ((lane >> 4) << 3);
                int bc = kk * 16 + ((lane >> 3) & 1) * 8;
                ldsm_x4(bh, sbase + (uint32_t)(SBBASE + (st * 2 + 0) * SST + br * 40 + bc) * 2);
                ldsm_x4(bl, sbase + (uint32_t)(SBBASE + (st * 2 + 1) * SST + br * 40 + bc) * 2);
#pragma unroll
                for (int n2 = 0; n2 < 2; n2++) {
                    int ni = ng * 2 + n2;
#pragma unroll
                    for (int mi = 0; mi < 2; mi++) {
                        mma16816(acc[mi][ni], a[0][mi], bh[n2 * 2], bh[n2 * 2 + 1]);
                        mma16816(acc[mi][ni], a[0][mi], bl[n2 * 2], bl[n2 * 2 + 1]);
                        mma16816(acc[mi][ni], a[1][mi], bh[n2 * 2], bh[n2 * 2 + 1]);
                    }
                }
            }
        }
    }

    const int rbase = m0 + wm * 32 + (lane >> 2);
#pragma unroll
    for (int mi = 0; mi < 2; mi++)
#pragma unroll
        for (int ni = 0; ni < 8; ni++) {
            const int col = n0 + wn * 64 + ni * 8 + (lane & 3) * 2;
#pragma unroll
            for (int h = 0; h < 2; h++) {
                int r = rbase + mi * 16 + h * 8;
                if (r >= M) continue;
                float2 t;
                t.x = acc[mi][ni][h * 2 + 0] * 0.0625f;
                t.y = acc[mi][ni][h * 2 + 1] * 0.0625f;
                *(float2*)(C + (size_t)r * N + col) = t;
            }
        }
}

// =====================================================================
// Fused softmax + AV + logits (proven). grid (2, 23, 96).
// =====================================================================
#define AV_PLO (128 * 136)
#define AV_BS  (2 * 128 * 136)
#define AV_BST (32 * 136)
__global__ __launch_bounds__(256) void av_fused_k(
    const float* __restrict__ S, const bf16* __restrict__ Vhi, const bf16* __restrict__ Vlo,
    const float* __restrict__ Vw,
    float* __restrict__ att, float* __restrict__ avo)
{
    extern __shared__ bf16 dyns[];
    const uint32_t sbase = (uint32_t)__cvta_generic_to_shared(dyns);

    const int tid = threadIdx.x, lane = tid & 31, w8 = tid >> 5;
    const int wm = w8 & 3, wn = w8 >> 2;
    const int m0 = blockIdx.y * 128, n0 = blockIdx.x * 128;
    const int bb = blockIdx.z;
    const int M = Bw * Tw;

    const int bkr = tid >> 4, bnq = tid & 15;
    auto cpB = [&](int k0, int st) {
#pragma unroll
        for (int hl = 0; hl < 2; hl++) {
            const bf16* bs = hl ? Vlo : Vhi;
            uint32_t bbuf = sbase + (uint32_t)(AV_BS + (st * 2 + hl) * AV_BST) * 2;
#pragma unroll
            for (int p = 0; p < 2; p++) {
                int row = p * 16 + bkr;
                cp16(bbuf + (uint32_t)(row * 136 + bnq * 8) * 2,
                     bs + ((size_t)bb * 128 + k0 + row) * 256 + n0 + bnq * 8);
            }
        }
    };

    cpB(0, 0); CP_COMMIT();
    cpB(32, 1); CP_COMMIT();

    for (int i = w8; i < 128; i += 8) {
        int m = m0 + i;
        int mc = m < M ? m : M - 1;
        int w_ = mc / 30, t_ = mc - w_ * 30;
        const float* src = S + (size_t)(w_ * 30 + t_) * (Bo * To) + bb * 100;
        float4 v = make_float4(-1e30f, -1e30f, -1e30f, -1e30f);
        if (lane < 25) v = *(const float4*)(src + lane * 4);

        float mx = fmaxf(fmaxf(v.x, v.y), fmaxf(v.z, v.w));
#pragma unroll
        for (int off = 16; off; off >>= 1) mx = fmaxf(mx, __shfl_xor_sync(0xffffffffu, mx, off));
        float4 e;
        e.x = __expf(v.x - mx); e.y = __expf(v.y - mx);
        e.z = __expf(v.z - mx); e.w = __expf(v.w - mx);
        float sm = e.x + e.y + e.z + e.w;
#pragma unroll
        for (int off = 16; off; off >>= 1) sm += __shfl_xor_sync(0xffffffffu, sm, off);
        const float inv = 1.f / sm;

        const int base = i * 136 + lane * 4;
        if (lane < 25) {
            float r0 = e.x * inv, r1 = e.y * inv, r2 = e.z * inv, r3 = e.w * inv;
            if (n0 == 0 && m < M) {
                float* dst = att + ((size_t)(w_ * 96 + bb) * 30 + t_) * 100 + lane * 4;
                dst[0] = r0; dst[1] = r1; dst[2] = r2; dst[3] = r3;
            }
            bf16 h0 = __float2bfloat16(r0), h1 = __float2bfloat16(r1);
            __nv_bfloat162 hv; hv.x = h0; hv.y = h1;
            *(uint32_t*)(dyns + base) = *(uint32_t*)&hv;
            *(uint32_t*)(dyns + AV_PLO + base) =
                pack2(r0 - __bfloat162float(h0), r1 - __bfloat162float(h1));
            h0 = __float2bfloat16(r2); h1 = __float2bfloat16(r3);
            hv.x = h0; hv.y = h1;
            *(uint32_t*)(dyns + base + 2) = *(uint32_t*)&hv;
            *(uint32_t*)(dyns + AV_PLO + base + 2) =
                pack2(r2 - __bfloat162float(h0), r3 - __bfloat162float(h1));
        } else {
            *(uint32_t*)(dyns + base) = 0u;
            *(uint32_t*)(dyns + base + 2) = 0u;
            *(uint32_t*)(dyns + AV_PLO + base) = 0u;
            *(uint32_t*)(dyns + AV_PLO + base + 2) = 0u;
        }
    }
    CP_WAIT1();
    __syncthreads();

    float acc[2][8][4];
#pragma unroll
    for (int i = 0; i < 2; i++)
#pragma unroll
        for (int j = 0; j < 8; j++)
#pragma unroll
            for (int q = 0; q < 4; q++) acc[i][j][q] = 0.f;

#pragma unroll
    for (int s = 0; s < 4; s++) {
        const int st = s & 1;
#pragma unroll
        for (int kk = 0; kk < 2; kk++) {
            uint32_t a[2][2][4];
            const int ar_ = (lane & 7) + ((lane >> 3) & 1) * 8;
            const int ac_ = s * 32 + kk * 16 + ((lane >> 4) << 3);
#pragma unroll
            for (int hl = 0; hl < 2; hl++)
#pragma unroll
                for (int mi = 0; mi < 2; mi++) {
                    int ar = wm * 32 + mi * 16 + ar_;
                    ldsm_x4(a[hl][mi], sbase + (uint32_t)(hl * AV_PLO + ar * 136 + ac_) * 2);
                }
#pragma unroll
            for (int ng = 0; ng < 4; ng++) {
                uint32_t bh[4], bl[4];
                int br = kk * 16 + (lane & 7) + ((lane >> 3) & 1) * 8;
                int bc = wn * 64 + ng * 16 + ((lane >> 4) << 3);
                ldsm_x4t(bh, sbase + (uint32_t)(AV_BS + (st * 2 + 0) * AV_BST + br * 136 + bc) * 2);
                ldsm_x4t(bl, sbase + (uint32_t)(AV_BS + (st * 2 + 1) * AV_BST + br * 136 + bc) * 2);
#pragma unroll
                for (int n2 = 0; n2 < 2; n2++) {
                    int ni = ng * 2 + n2;
#pragma unroll
                    for (int mi = 0; mi < 2; mi++) {
                        mma16816(acc[mi][ni], a[0][mi], bh[n2 * 2], bh[n2 * 2 + 1]);
                        mma16816(acc[mi][ni], a[0][mi], bl[n2 * 2], bl[n2 * 2 + 1]);
                        mma16816(acc[mi][ni], a[1][mi], bh[n2 * 2], bh[n2 * 2 + 1]);
                    }
                }
            }
        }
        __syncthreads();
        if (s + 2 < 4) {
            cpB((s + 2) * 32, st); CP_COMMIT(); CP_WAIT1();
        } else {
            CP_WAIT0();
        }
        __syncthreads();
    }

    const int rbase = m0 + wm * 32 + (lane >> 2);
#pragma unroll
    for (int mi = 0; mi < 2; mi++)
#pragma unroll
        for (int h = 0; h < 2; h++) {
            int r = rbase + mi * 16 + h * 8;
            bool ok = (r < M);
            int rc = ok ? r : M - 1;
            int w_ = rc / 30, t_ = rc - w_ * 30;
            float* prow = avo + ((size_t)(w_ * 96 + bb) * 30 + t_) * 256;
            const float* vwrow = Vw + (size_t)(w_ * 30 + t_) * 256;
            float s = 0.f;
#pragma unroll
            for (int ni = 0; ni < 8; ni++) {
                const int col = n0 + wn * 64 + ni * 8 + (lane & 3) * 2;
                float v0 = acc[mi][ni][h * 2 + 0];
                float v1 = acc[mi][ni][h * 2 + 1];
                if (ok) { prow[col] = v0; prow[col + 1] = v1; }
                float2 vw2 = *(const float2*)(vwrow + col);
                s += v0 * vw2.x + v1 * vw2.y;
            }
            s += __shfl_xor_sync(0xffffffffu, s, 1);
            s += __shfl_xor_sync(0xffffffffu, s, 2);
            if (ok && (lane & 3) == 0)
                atomicAdd(&logits_g[(size_t)(w_ * 96 + bb) * 30 + t_], s);
        }
}

// ---------------- loss ----------------
__global__ __launch_bounds__(32) void loss_terms_k(const float* __restrict__ mask)
{
    const int idx = blockIdx.x;
    const int w = idx / Tw, t = idx % Tw;
    const int lane = threadIdx.x;

    float m = -1e30f;
    for (int b = lane; b < Bo; b += 32)
        m = fmaxf(m, logits_g[((size_t)w * Bo + b) * Tw + t]);
#pragma unroll
    for (int off = 16; off; off >>= 1) m = fmaxf(m, __shfl_xor_sync(0xffffffffu, m, off));

    float s = 0.f;
    for (int b = lane; b < Bo; b += 32)
        s += __expf(logits_g[((size_t)w * Bo + b) * Tw + t] - m);
#pragma unroll
    for (int off = 16; off; off >>= 1) s += __shfl_xor_sync(0xffffffffu, s, off);
    float lse = m + __logf(s);

    float nm = (lane < Tw) ? (1.f - mask[w * Tw + lane]) : 0.f;
#pragma unroll
    for (int off = 16; off; off >>= 1) nm += __shfl_xor_sync(0xffffffffu, nm, off);

    if (lane == 0) {
        float diag = logits_g[((size_t)w * Bo + w) * Tw + t];
        terms_g[w * Tw + t] = (1.f - mask[w * Tw + t]) * (diag - lse) / (nm + 1e-6f);
    }
}

__global__ __launch_bounds__(256) void loss_final_k(float* __restrict__ out)
{
    __shared__ float sh[256];
    float s = 0.f;
    for (int i = threadIdx.x; i < Bw * Tw; i += 256) s += terms_g[i];
    sh[threadIdx.x] = s;
    __syncthreads();
#pragma unroll
    for (int off = 128; off; off >>= 1) {
        if (threadIdx.x < off) sh[threadIdx.x] += sh[threadIdx.x + off];
        __syncthreads();
    }
    if (threadIdx.x == 0) out[0] = -sh[0] / (float)Bw;
}

// ---------------- launch ----------------
static inline void* sym(const void* s) { void* p; cudaGetSymbolAddress(&p, s); return p; }

extern "C" void kernel_launch(void* const* d_in, const int* in_sizes, int n_in,
                              void* d_out, int out_size)
{
    const float* o    = (const float*)d_in[0];
    const float* u    = (const float*)d_in[1];
    const float* w    = (const float*)d_in[2];
    const float* mask = (const float*)d_in[3];
    const float* Wku  = (const float*)d_in[4];
    const float* bku  = (const float*)d_in[5];
    const float* Wkw  = (const float*)d_in[6];
    const float* bkw  = (const float*)d_in[7];
    const float* Wfo  = (const float*)d_in[8];
    const float* bfo  = (const float*)d_in[9];
    const float* Wfw  = (const float*)d_in[10];
    const float* bfw  = (const float*)d_in[11];

    float* out = (float*)d_out;
    float* att_out = out + 1;
    float* avo_out = out + 1 + (size_t)Bw * Bo * Tw * To;

    bf16 *Wkuhi = (bf16*)sym(Wkuhi_g), *Wkulo = (bf16*)sym(Wkulo_g);
    bf16 *Wkwhi = (bf16*)sym(Wkwhi_g), *Wkwlo = (bf16*)sym(Wkwlo_g);
    bf16 *Wfohi = (bf16*)sym(Wfohi_g), *Wfolo = (bf16*)sym(Wfolo_g);
    bf16 *Wfwhi = (bf16*)sym(Wfwhi_g), *Wfwlo = (bf16*)sym(Wfwlo_g);
    bf16 *Kuhi = (bf16*)sym(Kuhi_g), *Kulo = (bf16*)sym(Kulo_g);
    bf16 *Kwhi = (bf16*)sym(Kwhi_g), *Kwlo = (bf16*)sym(Kwlo_g);
    bf16 *Vohi = (bf16*)sym(Vohi_g), *Volo = (bf16*)sym(Volo_g);
    float *pVw = (float*)sym(Vw_g), *pS = (float*)sym(S_g);

    const int AV_SMEM = (AV_BS + 4 * AV_BST) * 2;
    cudaFuncSetAttribute(proj_k<1, false>, cudaFuncAttributeMaxDynamicSharedMemorySize, PROJ_SMEM);
    cudaFuncSetAttribute(proj_k<1, true>,  cudaFuncAttributeMaxDynamicSharedMemorySize, PROJ_SMEM);
    cudaFuncSetAttribute(s_mma_k,   cudaFuncAttributeMaxDynamicSharedMemorySize, S_SMEM);
    cudaFuncSetAttribute(av_fused_k, cudaFuncAttributeMaxDynamicSharedMemorySize, AV_SMEM);

    // weight splits
    auto grid4 = [](size_t n) { return (unsigned)((n / 4 + 255) / 256); };
    split_k<<<grid4((size_t)Du * Dk), 256>>>(Wku, Wkuhi, Wkulo, Du * Dk / 4);
    split_k<<<grid4((size_t)Dw * Dk), 256>>>(Wkw, Wkwhi, Wkwlo, Dw * Dk / 4);
    split_k<<<grid4((size_t)Do * Dv), 256>>>(Wfo, Wfohi, Wfolo, Do * Dv / 4);
    split_k<<<grid4((size_t)Dw * Dv), 256>>>(Wfw, Wfwhi, Wfwlo, Dw * Dv / 4);
    zero_logits_k<<<(Bw * Bo * Tw) / 1024, 1024>>>();

    // projections
    proj_k<1, false><<<dim3(2, 75), 256, PROJ_SMEM>>>(
        u, Wkuhi, Wkulo, nullptr, nullptr, bku, nullptr,
        nullptr, Kuhi, Kulo, Bo * To, Du, 0);
    // merged Kw (split out) + Vw (fp32 out): grid.x 0-1 -> Kw, 2-3 -> Vw
    proj_k<1, true><<<dim3(4, 23), 256, PROJ_SMEM>>>(
        w, Wkwhi, Wkwlo, Wfwhi, Wfwlo, bkw, bfw,
        pVw, Kwhi, Kwlo, Bw * Tw, Dw, 0);
    proj_k<1, false><<<dim3(2, 75), 256, PROJ_SMEM>>>(
        o, Wfohi, Wfolo, nullptr, nullptr, bfo, nullptr,
        nullptr, Vohi, Volo, Bo * To, Do, 1);

    // S = Kw @ Ku^T / 16
    s_mma_k<<<dim3(75, 23), 256, S_SMEM>>>(Kwhi, Kwlo, Kuhi, Kulo, pS, Bw * Tw, Bo * To, Dk);

    // fused softmax + AV + logits
    av_fused_k<<<dim3(2, 23, 96), 256, AV_SMEM>>>(pS, Vohi, Volo, pVw, att_out, avo_out);

    // loss
    loss_terms_k<<<Bw * Tw, 32>>>(mask);
    loss_final_k<<<1, 256>>>(out);
}